// round 14
// baseline (speedup 1.0000x reference)
#include <cuda_runtime.h>
#include <cuda_bf16.h>
#include <cuda_fp16.h>
#include <cstdint>

#define Nn 50000
#define Ee 800000
#define Hd 128
#define SCB 49       // scan blocks (ceil(Nn/1024))
#define PMAX 1600    // max stats-partial blocks (gemm12 uses 1563)
#define CH 8         // prop gather chunk (edges per stage)

// ---------------- scratch ----------------
__device__ int   g_deg[Nn];
__device__ int   g_cnt[Nn];
__device__ int   g_rowptr[Nn + 1];
__device__ int   g_tmpptr[Nn];
__device__ float g_dinv[Nn];
__device__ int2  g_epk[Ee];          // (src, weight-bits)
__device__ int   g_bsum[SCB];
__device__ int   g_boff[SCB];

__device__ __align__(256) float g_t1[Nn * Hd];
__device__ __align__(256) float g_t2[Nn * Hd];
__device__ __align__(256) float g_t3[Nn * Hd];
__device__ __align__(256) float g_out[Nn * Hd];

// pre-packed fp16 combined weights in Bs[kt][kpair][col] layout
__device__ __align__(256) uint32_t g_wh[3][32 * 8 * 128];

__device__ float g_s1[Nn * 3];
__device__ float g_s2[Nn * 3];
__device__ float g_s3[Nn * 3];

__device__ float g_part [PMAX * Hd];
__device__ float g_part2[PMAX * Hd];
__device__ float g_scale[Hd];
__device__ float g_shift[Hd];

// ---------------- helpers ----------------
__device__ __forceinline__ void mma_f16(float* c, const uint32_t* a, const uint32_t* b) {
    asm volatile(
        "mma.sync.aligned.m16n8k16.row.col.f32.f16.f16.f32 "
        "{%0,%1,%2,%3}, {%4,%5,%6,%7}, {%8,%9}, {%0,%1,%2,%3};"
        : "+f"(c[0]), "+f"(c[1]), "+f"(c[2]), "+f"(c[3])
        : "r"(a[0]), "r"(a[1]), "r"(a[2]), "r"(a[3]), "r"(b[0]), "r"(b[1]));
}
__device__ __forceinline__ uint32_t pack_h2(float a, float b) {
    __half2 h = __floats2half2_rn(a, b);
    return *(uint32_t*)&h;
}
__device__ __forceinline__ uint32_t smem_u32(const void* p) {
    uint32_t a;
    asm("{ .reg .u64 t; cvta.to.shared.u64 t, %1; cvt.u32.u64 %0, t; }" : "=r"(a) : "l"(p));
    return a;
}
__device__ __forceinline__ void cpa16(uint32_t saddr, const void* gptr) {
    asm volatile("cp.async.ca.shared.global [%0], [%1], 16;" :: "r"(saddr), "l"(gptr));
}
#define CP_COMMIT() asm volatile("cp.async.commit_group;" ::: "memory")
#define CP_WAIT1()  asm volatile("cp.async.wait_group 1;" ::: "memory")
#define CP_WAIT0()  asm volatile("cp.async.wait_group 0;" ::: "memory")

// ---------------- graph build ----------------
__global__ void k_init() {
    int i = blockIdx.x * blockDim.x + threadIdx.x;
    if (i < Nn) { g_deg[i] = 0; g_cnt[i] = 0; }
}

__global__ void k_count(const int* __restrict__ ei) {
    int e = blockIdx.x * blockDim.x + threadIdx.x;
    if (e < Ee) {
        int s = ei[e];
        int d = ei[e + Ee];
        if ((unsigned)s < Nn) atomicAdd(&g_deg[s], 1);
        if ((unsigned)d < Nn) atomicAdd(&g_cnt[d], 1);
    }
}

__global__ void k_scan1() {
    __shared__ int sd[1024];
    int b = blockIdx.x, tid = threadIdx.x;
    int i = b * 1024 + tid;
    int v = (i < Nn) ? g_cnt[i] : 0;
    sd[tid] = v;
    __syncthreads();
    for (int off = 1; off < 1024; off <<= 1) {
        int t = (tid >= off) ? sd[tid - off] : 0;
        __syncthreads();
        sd[tid] += t;
        __syncthreads();
    }
    if (i < Nn) g_rowptr[i + 1] = sd[tid];
    if (tid == 1023) g_bsum[b] = sd[1023];
}
__global__ void k_scan2() {
    __shared__ int sd[64];
    int t = threadIdx.x;
    int v = (t < SCB) ? g_bsum[t] : 0;
    sd[t] = v;
    __syncthreads();
    #pragma unroll
    for (int off = 1; off < 64; off <<= 1) {
        int u = (t >= off) ? sd[t - off] : 0;
        __syncthreads();
        sd[t] += u;
        __syncthreads();
    }
    if (t < SCB) g_boff[t] = sd[t] - v;   // exclusive
    if (t == 0) g_rowptr[0] = 0;
}
__global__ void k_scan3() {
    int i = blockIdx.x * blockDim.x + threadIdx.x;
    if (i < Nn) {
        int r = g_rowptr[i + 1] + g_boff[i >> 10];
        g_rowptr[i + 1] = r;
        g_tmpptr[i] = r - g_cnt[i];
        int d = g_deg[i];
        g_dinv[i] = (d > 0) ? rsqrtf((float)d) : 0.0f;
    }
}

__global__ void k_fill(const int* __restrict__ ei) {
    int e = blockIdx.x * blockDim.x + threadIdx.x;
    if (e < Ee) {
        int s = ei[e];
        int d = ei[e + Ee];
        if ((unsigned)s >= Nn || (unsigned)d >= Nn) return;
        int p = atomicAdd(&g_tmpptr[d], 1);
        float w = -g_dinv[s] * g_dinv[d];
        g_epk[p] = make_int2(s, __float_as_int(w));
    }
}

// pre-pack COMBINED weights -> half2 k-pair layout [kt][kpair][col].
// Monomial basis: block0: W0 - W2, block1: W1 - 3W3, block2: 2W2, block3: 4W3
__global__ void k_wpack(const float* __restrict__ W, uint32_t* __restrict__ out) {
    int idx = blockIdx.x * blockDim.x + threadIdx.x;
    if (idx < 32 * 8 * 128) {
        int col = idx & 127;
        int kp  = (idx >> 7) & 7;
        int kt  = idx >> 10;
        int blk = kt >> 3;
        int k0  = (kt & 7) * 16 + 2 * kp;
        float a0, a1;
        const float* Wb = W + blk * 128 * Hd;
        if (blk == 0) {
            const float* W2b = W + 2 * 128 * Hd;
            a0 = Wb[k0 * Hd + col]       - W2b[k0 * Hd + col];
            a1 = Wb[(k0 + 1) * Hd + col] - W2b[(k0 + 1) * Hd + col];
        } else if (blk == 1) {
            const float* W3b = W + 3 * 128 * Hd;
            a0 = Wb[k0 * Hd + col]       - 3.f * W3b[k0 * Hd + col];
            a1 = Wb[(k0 + 1) * Hd + col] - 3.f * W3b[(k0 + 1) * Hd + col];
        } else if (blk == 2) {
            a0 = 2.f * Wb[k0 * Hd + col];
            a1 = 2.f * Wb[(k0 + 1) * Hd + col];
        } else {
            a0 = 4.f * Wb[k0 * Hd + col];
            a1 = 4.f * Wb[(k0 + 1) * Hd + col];
        }
        out[idx] = pack_h2(a0, a1);
    }
}

// ---------------- propagation ----------------
__global__ void k_prop3(const float* __restrict__ hin,
                        const float* __restrict__ sub,
                        float* __restrict__ out) {
    int v = blockIdx.x * blockDim.x + threadIdx.x;
    if (v >= Nn) return;
    float a0 = 0.f, a1 = 0.f, a2 = 0.f;
    int b = g_rowptr[v], en = g_rowptr[v + 1];
    for (int i = b; i < en; i++) {
        int2 e = g_epk[i];
        float w = __int_as_float(e.y);
        const float* hp = hin + e.x * 3;
        a0 += w * hp[0]; a1 += w * hp[1]; a2 += w * hp[2];
    }
    float* o = out + v * 3;
    if (sub) {
        const float* sv = sub + v * 3;
        o[0] = 2.f * a0 - sv[0]; o[1] = 2.f * a1 - sv[1]; o[2] = 2.f * a2 - sv[2];
    } else {
        o[0] = a0; o[1] = a1; o[2] = a2;
    }
}

// warp per node; cp.async double-buffered gather pipeline.
// Each lane copies & consumes its own 16B of every row -> no intra-warp sync.
// bn != 0: out = sc * acc + sh * wsum
__global__ void k_prop128(const float* __restrict__ hin,
                          float* __restrict__ out,
                          const float* __restrict__ sc,
                          const float* __restrict__ sh,
                          int bn) {
    __shared__ __align__(16) float buf[4][2][CH][Hd];
    int wrp = threadIdx.x >> 5;
    int lane = threadIdx.x & 31;
    int v = blockIdx.x * 4 + wrp;
    if (v >= Nn) return;   // no block-level syncs in this kernel
    float4 sc4, sh4;
    if (bn) {
        sc4 = ((const float4*)sc)[lane];
        sh4 = ((const float4*)sh)[lane];
    }
    int b = g_rowptr[v], en = g_rowptr[v + 1];
    int deg = en - b;
    int nch = (deg + CH - 1) / CH;
    uint32_t sbase = smem_u32(&buf[wrp][0][0][0]) + lane * 16;
    const uint32_t BUFB = CH * Hd * 4;   // 4096 bytes per stage

    float4 acc = make_float4(0.f, 0.f, 0.f, 0.f);
    float wsum = 0.f;
    int2 ecur = make_int2(0, 0), enxt = make_int2(0, 0);

    // issue chunk c: coalesced edge load + CH row copies
    auto issue = [&](int c, int2& er) {
        int base = b + c * CH;
        int cnt = en - base; if (cnt > CH) cnt = CH;
        if (lane < cnt) er = g_epk[base + lane];
        uint32_t sa = sbase + (uint32_t)(c & 1) * BUFB;
        for (int j = 0; j < cnt; j++) {
            int src = __shfl_sync(0xffffffffu, er.x, j);
            cpa16(sa + (uint32_t)j * (Hd * 4), hin + src * Hd + lane * 4);
        }
        CP_COMMIT();
    };

    if (nch > 0) issue(0, ecur);
    for (int c = 0; c < nch; c++) {
        bool more = (c + 1 < nch);
        if (more) { issue(c + 1, enxt); CP_WAIT1(); }
        else      { CP_WAIT0(); }
        int base = b + c * CH;
        int cnt = en - base; if (cnt > CH) cnt = CH;
        int cb = c & 1;
        for (int j = 0; j < cnt; j++) {
            float w = __int_as_float(__shfl_sync(0xffffffffu, ecur.y, j));
            float4 g = *(const float4*)&buf[wrp][cb][j][lane * 4];
            acc.x += w * g.x; acc.y += w * g.y;
            acc.z += w * g.z; acc.w += w * g.w;
            wsum += w;
        }
        ecur = enxt;
    }

    float4 r;
    if (bn) {
        r.x = sc4.x * acc.x + sh4.x * wsum;
        r.y = sc4.y * acc.y + sh4.y * wsum;
        r.z = sc4.z * acc.z + sh4.z * wsum;
        r.w = sc4.w * acc.w + sh4.w * wsum;
    } else {
        r = acc;
    }
    *(float4*)(out + v * Hd + lane * 4) = r;
}

// ---------------- layer 1 GEMM: K=12 (+ fused stats partials) ----------------
__global__ void k_gemm12(const float* __restrict__ x,  const float* __restrict__ t1,
                         const float* __restrict__ t2, const float* __restrict__ t3,
                         const float* __restrict__ W,  const float* __restrict__ bias,
                         float* __restrict__ out) {
    __shared__ float sW[12 * Hd];
    int c = threadIdx.x;
    #pragma unroll
    for (int j = 0; j < 12; j++) sW[j * Hd + c] = W[j * Hd + c];
    __syncthreads();
    const int RPB = 32;
    int v0 = blockIdx.x * RPB;
    float bv = bias[c];
    float s = 0.f, s2 = 0.f;
    for (int r = 0; r < RPB; r++) {
        int v = v0 + r;
        if (v >= Nn) break;
        float a[12];
        #pragma unroll
        for (int f = 0; f < 3; f++) {
            a[f]     = x [v * 3 + f];
            a[3 + f] = t1[v * 3 + f];
            a[6 + f] = t2[v * 3 + f];
            a[9 + f] = t3[v * 3 + f];
        }
        float acc = bv;
        #pragma unroll
        for (int j = 0; j < 12; j++) acc += a[j] * sW[j * Hd + c];
        acc = (acc > 0.f) ? acc : 0.01f * acc;   // leaky relu
        out[v * Hd + c] = acc;
        s += acc; s2 += acc * acc;
    }
    g_part [blockIdx.x * Hd + c] = s;
    g_part2[blockIdx.x * Hd + c] = s2;
}

// ---------------- tensor-core GEMM (fp16 m16n8k16, 2-stage pipeline) --------
#define BM 128
#define BK 16
#define ASTR2 12
#define BSTR2 136

__global__ __launch_bounds__(256, 2)
void k_gemm_mma(const float* __restrict__ A0, const float* __restrict__ A1,
                const float* __restrict__ A2, const float* __restrict__ A3,
                const uint32_t* __restrict__ Wp, const float* __restrict__ bias,
                float* __restrict__ out,
                const float* __restrict__ scA, const float* __restrict__ shA,
                int mode) {
    __shared__ uint32_t As[2][BM][ASTR2];
    __shared__ uint32_t Bs[2][8][BSTR2];
    __shared__ float sred [8][64];
    __shared__ float sred2[8][64];
    __shared__ float rows2[2][BM];
    const float* Abuf[4] = {A0, A1, A2, A3};

    int tid = threadIdx.x;
    int wid = tid >> 5;
    int lane = tid & 31;
    int grp = lane >> 2;
    int tig = lane & 3;
    int m_base = (wid >> 1) * 32;
    int n_base = (wid & 1) * 64;
    int row0 = blockIdx.x * BM;

    float c[2][8][4];
    #pragma unroll
    for (int mi = 0; mi < 2; mi++)
        #pragma unroll
        for (int ni = 0; ni < 8; ni++)
            #pragma unroll
            for (int q = 0; q < 4; q++) c[mi][ni][q] = 0.f;

    int la_r  = tid >> 1;
    int la_c4 = (tid & 1) * 8;
    int lb_k  = tid >> 5;
    int lb_c4 = (tid & 31) * 4;

    auto load_stage = [&](int kt, uint4& ua, uint4& ub) {
        const float* A = Abuf[kt >> 3];
        int cb = (kt & 7) * BK;
        int gr = row0 + la_r;
        float4 v0 = make_float4(0.f,0.f,0.f,0.f), v1 = v0;
        if (gr < Nn) {
            const float4* src = (const float4*)(A + gr * Hd + cb + la_c4);
            v0 = src[0]; v1 = src[1];
        }
        if (scA && (kt >> 3) == 0) {
            float4 s0 = *(const float4*)(scA + cb + la_c4);
            float4 s1 = *(const float4*)(scA + cb + la_c4 + 4);
            float4 h0 = *(const float4*)(shA + cb + la_c4);
            float4 h1 = *(const float4*)(shA + cb + la_c4 + 4);
            v0.x = v0.x * s0.x + h0.x; v0.y = v0.y * s0.y + h0.y;
            v0.z = v0.z * s0.z + h0.z; v0.w = v0.w * s0.w + h0.w;
            v1.x = v1.x * s1.x + h1.x; v1.y = v1.y * s1.y + h1.y;
            v1.z = v1.z * s1.z + h1.z; v1.w = v1.w * s1.w + h1.w;
            if (gr >= Nn) { v0 = make_float4(0,0,0,0); v1 = v0; }
        }
        ua.x = pack_h2(v0.x, v0.y);
        ua.y = pack_h2(v0.z, v0.w);
        ua.z = pack_h2(v1.x, v1.y);
        ua.w = pack_h2(v1.z, v1.w);
        ub = *(const uint4*)(Wp + kt * 1024 + lb_k * 128 + lb_c4);
    };

    {
        uint4 ua, ub;
        load_stage(0, ua, ub);
        *(uint4*)&As[0][la_r][la_c4 >> 1] = ua;
        *(uint4*)&Bs[0][lb_k][lb_c4] = ub;
    }
    __syncthreads();

    for (int kt = 0; kt < 32; kt++) {
        int cur = kt & 1, nxt = cur ^ 1;
        uint4 na, nb;
        if (kt < 31) load_stage(kt + 1, na, nb);
        {
            uint32_t a[2][4], b[8][2];
            #pragma unroll
            for (int mi = 0; mi < 2; mi++) {
                int m0 = m_base + mi * 16 + grp;
                a[mi][0] = As[cur][m0][tig];
                a[mi][1] = As[cur][m0 + 8][tig];
                a[mi][2] = As[cur][m0][tig + 4];
                a[mi][3] = As[cur][m0 + 8][tig + 4];
            }
            #pragma unroll
            for (int ni = 0; ni < 8; ni++) {
                int nc = n_base + ni * 8 + grp;
                b[ni][0] = Bs[cur][tig][nc];
                b[ni][1] = Bs[cur][tig + 4][nc];
            }
            #pragma unroll
            for (int mi = 0; mi < 2; mi++)
                #pragma unroll
                for (int ni = 0; ni < 8; ni++)
                    mma_f16(c[mi][ni], a[mi], b[ni]);
        }
        if (kt < 31) {
            *(uint4*)&As[nxt][la_r][la_c4 >> 1] = na;
            *(uint4*)&Bs[nxt][lb_k][lb_c4] = nb;
        }
        __syncthreads();
    }

    // ---- bias + activation (zero invalid rows) ----
    #pragma unroll
    for (int mi = 0; mi < 2; mi++) {
        #pragma unroll
        for (int half = 0; half < 2; half++) {
            int row = row0 + m_base + mi * 16 + grp + half * 8;
            bool valid = row < Nn;
            #pragma unroll
            for (int ni = 0; ni < 8; ni++) {
                #pragma unroll
                for (int par = 0; par < 2; par++) {
                    int q = half * 2 + par;
                    int col = n_base + ni * 8 + tig * 2 + par;
                    float f = c[mi][ni][q] + __ldg(bias + col);
                    if (mode == 1)      f = (f > 0.f) ? f : 0.01f * f;
                    else if (mode == 2) f = fmaxf(f, 0.f);
                    c[mi][ni][q] = valid ? f : 0.f;
                }
            }
        }
    }

    float rscale[2][2] = {{1.f,1.f},{1.f,1.f}};

    if (mode != 0) {
        float ls[8][2], ls2[8][2];
        #pragma unroll
        for (int ni = 0; ni < 8; ni++)
            #pragma unroll
            for (int par = 0; par < 2; par++) {
                float s = 0.f, s2 = 0.f;
                #pragma unroll
                for (int mi = 0; mi < 2; mi++)
                    #pragma unroll
                    for (int half = 0; half < 2; half++) {
                        float f = c[mi][ni][half * 2 + par];
                        s += f; s2 += f * f;
                    }
                ls[ni][par] = s; ls2[ni][par] = s2;
            }
        #pragma unroll
        for (int off = 4; off < 32; off <<= 1) {
            #pragma unroll
            for (int ni = 0; ni < 8; ni++)
                #pragma unroll
                for (int par = 0; par < 2; par++) {
                    ls [ni][par] += __shfl_xor_sync(0xffffffffu, ls [ni][par], off);
                    ls2[ni][par] += __shfl_xor_sync(0xffffffffu, ls2[ni][par], off);
                }
        }
        if (lane < 4) {
            #pragma unroll
            for (int ni = 0; ni < 8; ni++)
                #pragma unroll
                for (int par = 0; par < 2; par++) {
                    sred [wid][ni * 8 + tig * 2 + par] = ls [ni][par];
                    sred2[wid][ni * 8 + tig * 2 + par] = ls2[ni][par];
                }
        }
        __syncthreads();
        if (tid < Hd) {
            int hf = tid >> 6, cl = tid & 63;
            float s = 0.f, s2 = 0.f;
            #pragma unroll
            for (int j = 0; j < 4; j++) {
                s  += sred [2 * j + hf][cl];
                s2 += sred2[2 * j + hf][cl];
            }
            g_part [blockIdx.x * Hd + tid] = s;
            g_part2[blockIdx.x * Hd + tid] = s2;
        }
    } else {
        #pragma unroll
        for (int mi = 0; mi < 2; mi++)
            #pragma unroll
            for (int half = 0; half < 2; half++) {
                float rsq = 0.f;
                #pragma unroll
                for (int ni = 0; ni < 8; ni++) {
                    float f0 = c[mi][ni][half * 2 + 0];
                    float f1 = c[mi][ni][half * 2 + 1];
                    rsq += f0 * f0 + f1 * f1;
                }
                rsq += __shfl_xor_sync(0xffffffffu, rsq, 1);
                rsq += __shfl_xor_sync(0xffffffffu, rsq, 2);
                if (tig == 0)
                    rows2[wid & 1][m_base + mi * 16 + grp + half * 8] = rsq;
            }
        __syncthreads();
        #pragma unroll
        for (int mi = 0; mi < 2; mi++)
            #pragma unroll
            for (int half = 0; half < 2; half++) {
                int rl = m_base + mi * 16 + grp + half * 8;
                float tot = rows2[0][rl] + rows2[1][rl];
                rscale[mi][half] = 1.f / fmaxf(sqrtf(tot), 1e-12f);
            }
    }

    // ---- store ----
    #pragma unroll
    for (int mi = 0; mi < 2; mi++) {
        #pragma unroll
        for (int half = 0; half < 2; half++) {
            int row = row0 + m_base + mi * 16 + grp + half * 8;
            if (row < Nn) {
                float rs = rscale[mi][half];
                #pragma unroll
                for (int ni = 0; ni < 8; ni++) {
                    int col = n_base + ni * 8 + tig * 2;
                    float f0 = c[mi][ni][half * 2 + 0] * rs;
                    float f1 = c[mi][ni][half * 2 + 1] * rs;
                    *(float2*)(out + row * Hd + col) = make_float2(f0, f1);
                }
            }
        }
    }
}

// ---------------- BN finalize (parallel: one block per channel) -------------
__global__ void k_bnfin(const float* __restrict__ gamma, const float* __restrict__ beta,
                        int nb) {
    int c = blockIdx.x;
    int t = threadIdx.x;
    float s = 0.f, s2 = 0.f;
    for (int b = t; b < nb; b += 256) {
        s  += g_part [b * Hd + c];
        s2 += g_part2[b * Hd + c];
    }
    __shared__ float ss[256], ss2[256];
    ss[t] = s; ss2[t] = s2;
    __syncthreads();
    #pragma unroll
    for (int off = 128; off; off >>= 1) {
        if (t < off) { ss[t] += ss[t + off]; ss2[t] += ss2[t + off]; }
        __syncthreads();
    }
    if (t == 0) {
        float m   = ss[0] / (float)Nn;
        float var = ss2[0] / (float)Nn - m * m;
        float inv = rsqrtf(var + 1e-5f);
        float sc  = gamma[c] * inv;
        g_scale[c] = sc;
        g_shift[c] = beta[c] - m * sc;
    }
}

// ---------------- host ----------------
extern "C" void kernel_launch(void* const* d_in, const int* in_sizes, int n_in,
                              void* d_out, int out_size) {
    const float* x  = (const float*)d_in[0];
    const int*   ei = (const int*)d_in[1];   // int32 (JAX x64 disabled)
    const float* W1 = (const float*)d_in[2];  const float* b1 = (const float*)d_in[3];
    const float* W2 = (const float*)d_in[4];  const float* b2 = (const float*)d_in[5];
    const float* W3 = (const float*)d_in[6];  const float* b3 = (const float*)d_in[7];
    const float* W4 = (const float*)d_in[8];  const float* b4 = (const float*)d_in[9];
    const float* g1 = (const float*)d_in[10]; const float* be1 = (const float*)d_in[11];
    const float* g2 = (const float*)d_in[12]; const float* be2 = (const float*)d_in[13];
    const float* g3 = (const float*)d_in[14]; const float* be3 = (const float*)d_in[15];

    float *p_t1, *p_t2, *p_t3, *p_out, *p_s1, *p_s2, *p_s3, *p_sc, *p_sh;
    uint32_t* p_wh;
    cudaGetSymbolAddress((void**)&p_t1,  g_t1);
    cudaGetSymbolAddress((void**)&p_t2,  g_t2);
    cudaGetSymbolAddress((void**)&p_t3,  g_t3);
    cudaGetSymbolAddress((void**)&p_out, g_out);
    cudaGetSymbolAddress((void**)&p_s1,  g_s1);
    cudaGetSymbolAddress((void**)&p_s2,  g_s2);
    cudaGetSymbolAddress((void**)&p_s3,  g_s3);
    cudaGetSymbolAddress((void**)&p_sc,  g_scale);
    cudaGetSymbolAddress((void**)&p_sh,  g_shift);
    cudaGetSymbolAddress((void**)&p_wh,  g_wh);

    const int TB = 256;
    const int WPW = 32 * 8 * 128;
    // graph build
    k_init <<<(Nn + TB - 1) / TB, TB>>>();
    k_count<<<(Ee + TB - 1) / TB, TB>>>(ei);
    k_scan1<<<SCB, 1024>>>();
    k_scan2<<<1, 64>>>();
    k_scan3<<<(Nn + TB - 1) / TB, TB>>>();
    k_fill <<<(Ee + TB - 1) / TB, TB>>>(ei);

    // pre-pack combined (monomial-basis) weights to fp16
    k_wpack<<<(WPW + TB - 1) / TB, TB>>>(W2, p_wh + 0 * WPW);
    k_wpack<<<(WPW + TB - 1) / TB, TB>>>(W3, p_wh + 1 * WPW);
    k_wpack<<<(WPW + TB - 1) / TB, TB>>>(W4, p_wh + 2 * WPW);

    int gP128 = (Nn + 3) / 4;
    int gGemm = (Nn + BM - 1) / BM;      // 391
    int g12   = (Nn + 31) / 32;          // 1563

    // layer 1 (F=3, Chebyshev form)
    k_prop3<<<(Nn + TB - 1) / TB, TB>>>(x, nullptr, p_s1);
    k_prop3<<<(Nn + TB - 1) / TB, TB>>>(p_s1, x, p_s2);
    k_prop3<<<(Nn + TB - 1) / TB, TB>>>(p_s2, p_s1, p_s3);
    k_gemm12<<<g12, Hd>>>(x, p_s1, p_s2, p_s3, W1, b1, p_out);
    k_bnfin<<<Hd, 256>>>(g1, be1, g12);

    // layer 2: p1 = L(bn(h)), p2 = L p1, p3 = L p2 (pure gathers)
    k_prop128<<<gP128, 128>>>(p_out, p_t1, p_sc, p_sh, 1);
    k_prop128<<<gP128, 128>>>(p_t1, p_t2, nullptr, nullptr, 0);
    k_prop128<<<gP128, 128>>>(p_t2, p_t3, nullptr, nullptr, 0);
    k_gemm_mma<<<gGemm, 256>>>(p_out, p_t1, p_t2, p_t3, p_wh + 0 * WPW, b2, p_out, p_sc, p_sh, 1);
    k_bnfin<<<Hd, 256>>>(g2, be2, gGemm);

    // layer 3
    k_prop128<<<gP128, 128>>>(p_out, p_t1, p_sc, p_sh, 1);
    k_prop128<<<gP128, 128>>>(p_t1, p_t2, nullptr, nullptr, 0);
    k_prop128<<<gP128, 128>>>(p_t2, p_t3, nullptr, nullptr, 0);
    k_gemm_mma<<<gGemm, 256>>>(p_out, p_t1, p_t2, p_t3, p_wh + 1 * WPW, b3, p_out, p_sc, p_sh, 2);
    k_bnfin<<<Hd, 256>>>(g3, be3, gGemm);

    // layer 4: props + GEMM with fused row-normalize, straight to d_out
    k_prop128<<<gP128, 128>>>(p_out, p_t1, p_sc, p_sh, 1);
    k_prop128<<<gP128, 128>>>(p_t1, p_t2, nullptr, nullptr, 0);
    k_prop128<<<gP128, 128>>>(p_t2, p_t3, nullptr, nullptr, 0);
    k_gemm_mma<<<gGemm, 256>>>(p_out, p_t1, p_t2, p_t3, p_wh + 2 * WPW, b4, (float*)d_out,
                               p_sc, p_sh, 0);
}

// round 15
// speedup vs baseline: 1.3382x; 1.3382x over previous
#include <cuda_runtime.h>
#include <cuda_bf16.h>
#include <cuda_fp16.h>
#include <cstdint>

#define Nn 50000
#define Ee 800000
#define Hd 128
#define SCB 49       // scan blocks (ceil(Nn/1024))
#define PMAX 1600    // max stats-partial blocks (gemm12 uses 1563)

// ---------------- scratch ----------------
__device__ int   g_deg[Nn];
__device__ int   g_cnt[Nn];
__device__ int   g_rowptr[Nn + 1];
__device__ int   g_tmpptr[Nn];
__device__ float g_dinv[Nn];
__device__ int2  g_epk[Ee];          // (src, weight-bits)
__device__ int   g_bsum[SCB];
__device__ int   g_boff[SCB];

__device__ __align__(256) float g_t1[Nn * Hd];
__device__ __align__(256) float g_t2[Nn * Hd];
__device__ __align__(256) float g_t3[Nn * Hd];
__device__ __align__(256) float g_out[Nn * Hd];

// pre-packed fp16 combined weights in Bs[kt][kpair][col] layout
__device__ __align__(256) uint32_t g_wh[3][32 * 8 * 128];

__device__ float g_s1[Nn * 3];
__device__ float g_s2[Nn * 3];
__device__ float g_s3[Nn * 3];

__device__ float g_part [PMAX * Hd];
__device__ float g_part2[PMAX * Hd];
__device__ float g_scale[Hd];
__device__ float g_shift[Hd];

// ---------------- helpers ----------------
__device__ __forceinline__ void mma_f16(float* c, const uint32_t* a, const uint32_t* b) {
    asm volatile(
        "mma.sync.aligned.m16n8k16.row.col.f32.f16.f16.f32 "
        "{%0,%1,%2,%3}, {%4,%5,%6,%7}, {%8,%9}, {%0,%1,%2,%3};"
        : "+f"(c[0]), "+f"(c[1]), "+f"(c[2]), "+f"(c[3])
        : "r"(a[0]), "r"(a[1]), "r"(a[2]), "r"(a[3]), "r"(b[0]), "r"(b[1]));
}
__device__ __forceinline__ uint32_t pack_h2(float a, float b) {
    __half2 h = __floats2half2_rn(a, b);
    return *(uint32_t*)&h;
}

// ---------------- graph build ----------------
__global__ void k_init() {
    int i = blockIdx.x * blockDim.x + threadIdx.x;
    if (i < Nn) { g_deg[i] = 0; g_cnt[i] = 0; }
}

__global__ void k_count(const int* __restrict__ ei) {
    int e = blockIdx.x * blockDim.x + threadIdx.x;
    if (e < Ee) {
        int s = ei[e];
        int d = ei[e + Ee];
        if ((unsigned)s < Nn) atomicAdd(&g_deg[s], 1);
        if ((unsigned)d < Nn) atomicAdd(&g_cnt[d], 1);
    }
}

__global__ void k_scan1() {
    __shared__ int sd[1024];
    int b = blockIdx.x, tid = threadIdx.x;
    int i = b * 1024 + tid;
    int v = (i < Nn) ? g_cnt[i] : 0;
    sd[tid] = v;
    __syncthreads();
    for (int off = 1; off < 1024; off <<= 1) {
        int t = (tid >= off) ? sd[tid - off] : 0;
        __syncthreads();
        sd[tid] += t;
        __syncthreads();
    }
    if (i < Nn) g_rowptr[i + 1] = sd[tid];
    if (tid == 1023) g_bsum[b] = sd[1023];
}
// parallel scan over 49 block sums (64 threads)
__global__ void k_scan2() {
    __shared__ int sd[64];
    int t = threadIdx.x;
    int v = (t < SCB) ? g_bsum[t] : 0;
    sd[t] = v;
    __syncthreads();
    #pragma unroll
    for (int off = 1; off < 64; off <<= 1) {
        int u = (t >= off) ? sd[t - off] : 0;
        __syncthreads();
        sd[t] += u;
        __syncthreads();
    }
    if (t < SCB) g_boff[t] = sd[t] - v;   // exclusive
    if (t == 0) g_rowptr[0] = 0;
}
// scan finalize + dinv (deg final after k_count)
__global__ void k_scan3() {
    int i = blockIdx.x * blockDim.x + threadIdx.x;
    if (i < Nn) {
        int r = g_rowptr[i + 1] + g_boff[i >> 10];
        g_rowptr[i + 1] = r;
        g_tmpptr[i] = r - g_cnt[i];
        int d = g_deg[i];
        g_dinv[i] = (d > 0) ? rsqrtf((float)d) : 0.0f;
    }
}

__global__ void k_fill(const int* __restrict__ ei) {
    int e = blockIdx.x * blockDim.x + threadIdx.x;
    if (e < Ee) {
        int s = ei[e];
        int d = ei[e + Ee];
        if ((unsigned)s >= Nn || (unsigned)d >= Nn) return;
        int p = atomicAdd(&g_tmpptr[d], 1);
        float w = -g_dinv[s] * g_dinv[d];
        g_epk[p] = make_int2(s, __float_as_int(w));
    }
}

// pre-pack COMBINED weights for all 3 layers in one launch.
// Monomial basis: block0: W0 - W2, block1: W1 - 3W3, block2: 2W2, block3: 4W3
__global__ void k_wpack3(const float* __restrict__ Wa, const float* __restrict__ Wb_,
                         const float* __restrict__ Wc, uint32_t* __restrict__ out) {
    int gidx = blockIdx.x * blockDim.x + threadIdx.x;
    const int WPW = 32 * 8 * 128;
    if (gidx >= 3 * WPW) return;
    int layer = gidx / WPW;
    int idx   = gidx - layer * WPW;
    const float* W = (layer == 0) ? Wa : (layer == 1) ? Wb_ : Wc;
    int col = idx & 127;
    int kp  = (idx >> 7) & 7;
    int kt  = idx >> 10;
    int blk = kt >> 3;
    int k0  = (kt & 7) * 16 + 2 * kp;
    float a0, a1;
    const float* Wb = W + blk * 128 * Hd;
    if (blk == 0) {
        const float* W2b = W + 2 * 128 * Hd;
        a0 = Wb[k0 * Hd + col]       - W2b[k0 * Hd + col];
        a1 = Wb[(k0 + 1) * Hd + col] - W2b[(k0 + 1) * Hd + col];
    } else if (blk == 1) {
        const float* W3b = W + 3 * 128 * Hd;
        a0 = Wb[k0 * Hd + col]       - 3.f * W3b[k0 * Hd + col];
        a1 = Wb[(k0 + 1) * Hd + col] - 3.f * W3b[(k0 + 1) * Hd + col];
    } else if (blk == 2) {
        a0 = 2.f * Wb[k0 * Hd + col];
        a1 = 2.f * Wb[(k0 + 1) * Hd + col];
    } else {
        a0 = 4.f * Wb[k0 * Hd + col];
        a1 = 4.f * Wb[(k0 + 1) * Hd + col];
    }
    out[gidx] = pack_h2(a0, a1);
}

// ---------------- propagation ----------------
// layer-1 (F=3) props stay in Chebyshev form (cheap)
__global__ void k_prop3(const float* __restrict__ hin,
                        const float* __restrict__ sub,
                        float* __restrict__ out) {
    int v = blockIdx.x * blockDim.x + threadIdx.x;
    if (v >= Nn) return;
    float a0 = 0.f, a1 = 0.f, a2 = 0.f;
    int b = g_rowptr[v], en = g_rowptr[v + 1];
    for (int i = b; i < en; i++) {
        int2 e = g_epk[i];
        float w = __int_as_float(e.y);
        const float* hp = hin + e.x * 3;
        a0 += w * hp[0]; a1 += w * hp[1]; a2 += w * hp[2];
    }
    float* o = out + v * 3;
    if (sub) {
        const float* sv = sub + v * 3;
        o[0] = 2.f * a0 - sv[0]; o[1] = 2.f * a1 - sv[1]; o[2] = 2.f * a2 - sv[2];
    } else {
        o[0] = a0; o[1] = a1; o[2] = a2;
    }
}

// warp per node, monomial basis: pure gather (+ optional analytic BN on input).
// bn != 0: out = sc * acc + sh * wsum
__global__ void k_prop128(const float* __restrict__ hin,
                          float* __restrict__ out,
                          const float* __restrict__ sc,
                          const float* __restrict__ sh,
                          int bn) {
    int v = blockIdx.x * 4 + (threadIdx.x >> 5);
    if (v >= Nn) return;
    int lane = threadIdx.x & 31;
    float4 sc4, sh4;
    if (bn) {
        sc4 = ((const float4*)sc)[lane];
        sh4 = ((const float4*)sh)[lane];
    }
    int b = g_rowptr[v], en = g_rowptr[v + 1];
    float4 acc = make_float4(0.f, 0.f, 0.f, 0.f);
    float wsum = 0.f;
    int i = b;
    for (; i + 1 < en; i += 2) {
        int2 e0 = g_epk[i];
        int2 e1 = g_epk[i + 1];
        float w0 = __int_as_float(e0.y);
        float w1 = __int_as_float(e1.y);
        float4 v0 = *(const float4*)(hin + e0.x * Hd + lane * 4);
        float4 v1 = *(const float4*)(hin + e1.x * Hd + lane * 4);
        acc.x += w0 * v0.x + w1 * v1.x;
        acc.y += w0 * v0.y + w1 * v1.y;
        acc.z += w0 * v0.z + w1 * v1.z;
        acc.w += w0 * v0.w + w1 * v1.w;
        wsum += w0 + w1;
    }
    if (i < en) {
        int2 e = g_epk[i];
        float w = __int_as_float(e.y);
        float4 g = *(const float4*)(hin + e.x * Hd + lane * 4);
        acc.x += w * g.x; acc.y += w * g.y; acc.z += w * g.z; acc.w += w * g.w;
        wsum += w;
    }
    float4 r;
    if (bn) {
        r.x = sc4.x * acc.x + sh4.x * wsum;
        r.y = sc4.y * acc.y + sh4.y * wsum;
        r.z = sc4.z * acc.z + sh4.z * wsum;
        r.w = sc4.w * acc.w + sh4.w * wsum;
    } else {
        r = acc;
    }
    *(float4*)(out + v * Hd + lane * 4) = r;
}

// ---------------- layer 1 GEMM: K=12 (+ fused stats partials) ----------------
__global__ void k_gemm12(const float* __restrict__ x,  const float* __restrict__ t1,
                         const float* __restrict__ t2, const float* __restrict__ t3,
                         const float* __restrict__ W,  const float* __restrict__ bias,
                         float* __restrict__ out) {
    __shared__ float sW[12 * Hd];
    int c = threadIdx.x;
    #pragma unroll
    for (int j = 0; j < 12; j++) sW[j * Hd + c] = W[j * Hd + c];
    __syncthreads();
    const int RPB = 32;
    int v0 = blockIdx.x * RPB;
    float bv = bias[c];
    float s = 0.f, s2 = 0.f;
    for (int r = 0; r < RPB; r++) {
        int v = v0 + r;
        if (v >= Nn) break;
        float a[12];
        #pragma unroll
        for (int f = 0; f < 3; f++) {
            a[f]     = x [v * 3 + f];
            a[3 + f] = t1[v * 3 + f];
            a[6 + f] = t2[v * 3 + f];
            a[9 + f] = t3[v * 3 + f];
        }
        float acc = bv;
        #pragma unroll
        for (int j = 0; j < 12; j++) acc += a[j] * sW[j * Hd + c];
        acc = (acc > 0.f) ? acc : 0.01f * acc;   // leaky relu
        out[v * Hd + c] = acc;
        s += acc; s2 += acc * acc;
    }
    g_part [blockIdx.x * Hd + c] = s;
    g_part2[blockIdx.x * Hd + c] = s2;
}

// ---------------- tensor-core GEMM (fp16 m16n8k16, 2-stage pipeline) --------
// A = [h, p1, p2, p3], B pre-packed combined weights.
// mode: 1 = leaky+stats, 2 = relu+stats, 0 = no-act + row-L2-normalize
#define BM 128
#define BK 16
#define ASTR2 12
#define BSTR2 136

__global__ __launch_bounds__(256, 2)
void k_gemm_mma(const float* __restrict__ A0, const float* __restrict__ A1,
                const float* __restrict__ A2, const float* __restrict__ A3,
                const uint32_t* __restrict__ Wp, const float* __restrict__ bias,
                float* __restrict__ out,
                const float* __restrict__ scA, const float* __restrict__ shA,
                int mode) {
    __shared__ uint32_t As[2][BM][ASTR2];
    __shared__ uint32_t Bs[2][8][BSTR2];
    __shared__ float sred [8][64];
    __shared__ float sred2[8][64];
    __shared__ float rows2[2][BM];
    const float* Abuf[4] = {A0, A1, A2, A3};

    int tid = threadIdx.x;
    int wid = tid >> 5;
    int lane = tid & 31;
    int grp = lane >> 2;
    int tig = lane & 3;
    int m_base = (wid >> 1) * 32;
    int n_base = (wid & 1) * 64;
    int row0 = blockIdx.x * BM;

    float c[2][8][4];
    #pragma unroll
    for (int mi = 0; mi < 2; mi++)
        #pragma unroll
        for (int ni = 0; ni < 8; ni++)
            #pragma unroll
            for (int q = 0; q < 4; q++) c[mi][ni][q] = 0.f;

    int la_r  = tid >> 1;
    int la_c4 = (tid & 1) * 8;
    int lb_k  = tid >> 5;
    int lb_c4 = (tid & 31) * 4;

    auto load_stage = [&](int kt, uint4& ua, uint4& ub) {
        const float* A = Abuf[kt >> 3];
        int cb = (kt & 7) * BK;
        int gr = row0 + la_r;
        float4 v0 = make_float4(0.f,0.f,0.f,0.f), v1 = v0;
        if (gr < Nn) {
            const float4* src = (const float4*)(A + gr * Hd + cb + la_c4);
            v0 = src[0]; v1 = src[1];
        }
        if (scA && (kt >> 3) == 0) {
            float4 s0 = *(const float4*)(scA + cb + la_c4);
            float4 s1 = *(const float4*)(scA + cb + la_c4 + 4);
            float4 h0 = *(const float4*)(shA + cb + la_c4);
            float4 h1 = *(const float4*)(shA + cb + la_c4 + 4);
            v0.x = v0.x * s0.x + h0.x; v0.y = v0.y * s0.y + h0.y;
            v0.z = v0.z * s0.z + h0.z; v0.w = v0.w * s0.w + h0.w;
            v1.x = v1.x * s1.x + h1.x; v1.y = v1.y * s1.y + h1.y;
            v1.z = v1.z * s1.z + h1.z; v1.w = v1.w * s1.w + h1.w;
            if (gr >= Nn) { v0 = make_float4(0,0,0,0); v1 = v0; }
        }
        ua.x = pack_h2(v0.x, v0.y);
        ua.y = pack_h2(v0.z, v0.w);
        ua.z = pack_h2(v1.x, v1.y);
        ua.w = pack_h2(v1.z, v1.w);
        ub = *(const uint4*)(Wp + kt * 1024 + lb_k * 128 + lb_c4);
    };

    {
        uint4 ua, ub;
        load_stage(0, ua, ub);
        *(uint4*)&As[0][la_r][la_c4 >> 1] = ua;
        *(uint4*)&Bs[0][lb_k][lb_c4] = ub;
    }
    __syncthreads();

    for (int kt = 0; kt < 32; kt++) {
        int cur = kt & 1, nxt = cur ^ 1;
        uint4 na, nb;
        if (kt < 31) load_stage(kt + 1, na, nb);
        {
            uint32_t a[2][4], b[8][2];
            #pragma unroll
            for (int mi = 0; mi < 2; mi++) {
                int m0 = m_base + mi * 16 + grp;
                a[mi][0] = As[cur][m0][tig];
                a[mi][1] = As[cur][m0 + 8][tig];
                a[mi][2] = As[cur][m0][tig + 4];
                a[mi][3] = As[cur][m0 + 8][tig + 4];
            }
            #pragma unroll
            for (int ni = 0; ni < 8; ni++) {
                int nc = n_base + ni * 8 + grp;
                b[ni][0] = Bs[cur][tig][nc];
                b[ni][1] = Bs[cur][tig + 4][nc];
            }
            #pragma unroll
            for (int mi = 0; mi < 2; mi++)
                #pragma unroll
                for (int ni = 0; ni < 8; ni++)
                    mma_f16(c[mi][ni], a[mi], b[ni]);
        }
        if (kt < 31) {
            *(uint4*)&As[nxt][la_r][la_c4 >> 1] = na;
            *(uint4*)&Bs[nxt][lb_k][lb_c4] = nb;
        }
        __syncthreads();
    }

    // ---- bias + activation (zero invalid rows) ----
    #pragma unroll
    for (int mi = 0; mi < 2; mi++) {
        #pragma unroll
        for (int half = 0; half < 2; half++) {
            int row = row0 + m_base + mi * 16 + grp + half * 8;
            bool valid = row < Nn;
            #pragma unroll
            for (int ni = 0; ni < 8; ni++) {
                #pragma unroll
                for (int par = 0; par < 2; par++) {
                    int q = half * 2 + par;
                    int col = n_base + ni * 8 + tig * 2 + par;
                    float f = c[mi][ni][q] + __ldg(bias + col);
                    if (mode == 1)      f = (f > 0.f) ? f : 0.01f * f;
                    else if (mode == 2) f = fmaxf(f, 0.f);
                    c[mi][ni][q] = valid ? f : 0.f;
                }
            }
        }
    }

    float rscale[2][2] = {{1.f,1.f},{1.f,1.f}};

    if (mode != 0) {
        float ls[8][2], ls2[8][2];
        #pragma unroll
        for (int ni = 0; ni < 8; ni++)
            #pragma unroll
            for (int par = 0; par < 2; par++) {
                float s = 0.f, s2 = 0.f;
                #pragma unroll
                for (int mi = 0; mi < 2; mi++)
                    #pragma unroll
                    for (int half = 0; half < 2; half++) {
                        float f = c[mi][ni][half * 2 + par];
                        s += f; s2 += f * f;
                    }
                ls[ni][par] = s; ls2[ni][par] = s2;
            }
        #pragma unroll
        for (int off = 4; off < 32; off <<= 1) {
            #pragma unroll
            for (int ni = 0; ni < 8; ni++)
                #pragma unroll
                for (int par = 0; par < 2; par++) {
                    ls [ni][par] += __shfl_xor_sync(0xffffffffu, ls [ni][par], off);
                    ls2[ni][par] += __shfl_xor_sync(0xffffffffu, ls2[ni][par], off);
                }
        }
        if (lane < 4) {
            #pragma unroll
            for (int ni = 0; ni < 8; ni++)
                #pragma unroll
                for (int par = 0; par < 2; par++) {
                    sred [wid][ni * 8 + tig * 2 + par] = ls [ni][par];
                    sred2[wid][ni * 8 + tig * 2 + par] = ls2[ni][par];
                }
        }
        __syncthreads();
        if (tid < Hd) {
            int hf = tid >> 6, cl = tid & 63;
            float s = 0.f, s2 = 0.f;
            #pragma unroll
            for (int j = 0; j < 4; j++) {
                s  += sred [2 * j + hf][cl];
                s2 += sred2[2 * j + hf][cl];
            }
            g_part [blockIdx.x * Hd + tid] = s;
            g_part2[blockIdx.x * Hd + tid] = s2;
        }
    } else {
        #pragma unroll
        for (int mi = 0; mi < 2; mi++)
            #pragma unroll
            for (int half = 0; half < 2; half++) {
                float rsq = 0.f;
                #pragma unroll
                for (int ni = 0; ni < 8; ni++) {
                    float f0 = c[mi][ni][half * 2 + 0];
                    float f1 = c[mi][ni][half * 2 + 1];
                    rsq += f0 * f0 + f1 * f1;
                }
                rsq += __shfl_xor_sync(0xffffffffu, rsq, 1);
                rsq += __shfl_xor_sync(0xffffffffu, rsq, 2);
                if (tig == 0)
                    rows2[wid & 1][m_base + mi * 16 + grp + half * 8] = rsq;
            }
        __syncthreads();
        #pragma unroll
        for (int mi = 0; mi < 2; mi++)
            #pragma unroll
            for (int half = 0; half < 2; half++) {
                int rl = m_base + mi * 16 + grp + half * 8;
                float tot = rows2[0][rl] + rows2[1][rl];
                rscale[mi][half] = 1.f / fmaxf(sqrtf(tot), 1e-12f);
            }
    }

    // ---- store ----
    #pragma unroll
    for (int mi = 0; mi < 2; mi++) {
        #pragma unroll
        for (int half = 0; half < 2; half++) {
            int row = row0 + m_base + mi * 16 + grp + half * 8;
            if (row < Nn) {
                float rs = rscale[mi][half];
                #pragma unroll
                for (int ni = 0; ni < 8; ni++) {
                    int col = n_base + ni * 8 + tig * 2;
                    float f0 = c[mi][ni][half * 2 + 0] * rs;
                    float f1 = c[mi][ni][half * 2 + 1] * rs;
                    *(float2*)(out + row * Hd + col) = make_float2(f0, f1);
                }
            }
        }
    }
}

// ---------------- BN finalize (parallel: one block per channel) -------------
__global__ void k_bnfin(const float* __restrict__ gamma, const float* __restrict__ beta,
                        int nb) {
    int c = blockIdx.x;
    int t = threadIdx.x;
    float s = 0.f, s2 = 0.f;
    for (int b = t; b < nb; b += 256) {
        s  += g_part [b * Hd + c];
        s2 += g_part2[b * Hd + c];
    }
    __shared__ float ss[256], ss2[256];
    ss[t] = s; ss2[t] = s2;
    __syncthreads();
    #pragma unroll
    for (int off = 128; off; off >>= 1) {
        if (t < off) { ss[t] += ss[t + off]; ss2[t] += ss2[t + off]; }
        __syncthreads();
    }
    if (t == 0) {
        float m   = ss[0] / (float)Nn;
        float var = ss2[0] / (float)Nn - m * m;
        float inv = rsqrtf(var + 1e-5f);
        float sc  = gamma[c] * inv;
        g_scale[c] = sc;
        g_shift[c] = beta[c] - m * sc;
    }
}

// ---------------- host ----------------
extern "C" void kernel_launch(void* const* d_in, const int* in_sizes, int n_in,
                              void* d_out, int out_size) {
    const float* x  = (const float*)d_in[0];
    const int*   ei = (const int*)d_in[1];   // int32 (JAX x64 disabled)
    const float* W1 = (const float*)d_in[2];  const float* b1 = (const float*)d_in[3];
    const float* W2 = (const float*)d_in[4];  const float* b2 = (const float*)d_in[5];
    const float* W3 = (const float*)d_in[6];  const float* b3 = (const float*)d_in[7];
    const float* W4 = (const float*)d_in[8];  const float* b4 = (const float*)d_in[9];
    const float* g1 = (const float*)d_in[10]; const float* be1 = (const float*)d_in[11];
    const float* g2 = (const float*)d_in[12]; const float* be2 = (const float*)d_in[13];
    const float* g3 = (const float*)d_in[14]; const float* be3 = (const float*)d_in[15];

    float *p_t1, *p_t2, *p_t3, *p_out, *p_s1, *p_s2, *p_s3, *p_sc, *p_sh;
    uint32_t* p_wh;
    cudaGetSymbolAddress((void**)&p_t1,  g_t1);
    cudaGetSymbolAddress((void**)&p_t2,  g_t2);
    cudaGetSymbolAddress((void**)&p_t3,  g_t3);
    cudaGetSymbolAddress((void**)&p_out, g_out);
    cudaGetSymbolAddress((void**)&p_s1,  g_s1);
    cudaGetSymbolAddress((void**)&p_s2,  g_s2);
    cudaGetSymbolAddress((void**)&p_s3,  g_s3);
    cudaGetSymbolAddress((void**)&p_sc,  g_scale);
    cudaGetSymbolAddress((void**)&p_sh,  g_shift);
    cudaGetSymbolAddress((void**)&p_wh,  g_wh);

    const int TB = 256;
    const int WPW = 32 * 8 * 128;
    // graph build
    k_init <<<(Nn + TB - 1) / TB, TB>>>();
    k_count<<<(Ee + TB - 1) / TB, TB>>>(ei);
    k_scan1<<<SCB, 1024>>>();
    k_scan2<<<1, 64>>>();
    k_scan3<<<(Nn + TB - 1) / TB, TB>>>();
    k_fill <<<(Ee + TB - 1) / TB, TB>>>(ei);

    // pre-pack combined (monomial-basis) weights for all layers, one launch
    k_wpack3<<<(3 * WPW + TB - 1) / TB, TB>>>(W2, W3, W4, p_wh);

    int gP128 = (Nn + 3) / 4;
    int gGemm = (Nn + BM - 1) / BM;      // 391
    int g12   = (Nn + 31) / 32;          // 1563

    // layer 1 (F=3, Chebyshev form)
    k_prop3<<<(Nn + TB - 1) / TB, TB>>>(x, nullptr, p_s1);
    k_prop3<<<(Nn + TB - 1) / TB, TB>>>(p_s1, x, p_s2);
    k_prop3<<<(Nn + TB - 1) / TB, TB>>>(p_s2, p_s1, p_s3);
    k_gemm12<<<g12, Hd>>>(x, p_s1, p_s2, p_s3, W1, b1, p_out);
    k_bnfin<<<Hd, 256>>>(g1, be1, g12);

    // layer 2: p1 = L(bn(h)), p2 = L p1, p3 = L p2 (pure gathers)
    k_prop128<<<gP128, 128>>>(p_out, p_t1, p_sc, p_sh, 1);
    k_prop128<<<gP128, 128>>>(p_t1, p_t2, nullptr, nullptr, 0);
    k_prop128<<<gP128, 128>>>(p_t2, p_t3, nullptr, nullptr, 0);
    k_gemm_mma<<<gGemm, 256>>>(p_out, p_t1, p_t2, p_t3, p_wh + 0 * WPW, b2, p_out, p_sc, p_sh, 1);
    k_bnfin<<<Hd, 256>>>(g2, be2, gGemm);

    // layer 3
    k_prop128<<<gP128, 128>>>(p_out, p_t1, p_sc, p_sh, 1);
    k_prop128<<<gP128, 128>>>(p_t1, p_t2, nullptr, nullptr, 0);
    k_prop128<<<gP128, 128>>>(p_t2, p_t3, nullptr, nullptr, 0);
    k_gemm_mma<<<gGemm, 256>>>(p_out, p_t1, p_t2, p_t3, p_wh + 1 * WPW, b3, p_out, p_sc, p_sh, 2);
    k_bnfin<<<Hd, 256>>>(g3, be3, gGemm);

    // layer 4: props + GEMM with fused row-normalize, straight to d_out
    k_prop128<<<gP128, 128>>>(p_out, p_t1, p_sc, p_sh, 1);
    k_prop128<<<gP128, 128>>>(p_t1, p_t2, nullptr, nullptr, 0);
    k_prop128<<<gP128, 128>>>(p_t2, p_t3, nullptr, nullptr, 0);
    k_gemm_mma<<<gGemm, 256>>>(p_out, p_t1, p_t2, p_t3, p_wh + 2 * WPW, b4, (float*)d_out,
                               p_sc, p_sh, 0);
}

// round 16
// speedup vs baseline: 1.3472x; 1.0067x over previous
#include <cuda_runtime.h>
#include <cuda_bf16.h>
#include <cuda_fp16.h>
#include <cstdint>

#define Nn 50000
#define Ee 800000
#define Hd 128
#define SCB 49       // scan blocks (ceil(Nn/1024))
#define PMAX 1600    // max stats-partial blocks (gemm12 uses 1563)

// ---------------- scratch ----------------
__device__ int   g_deg[Nn];
__device__ int   g_cnt[Nn];
__device__ int   g_rowptr[Nn + 1];
__device__ int   g_tmpptr[Nn];
__device__ float g_dinv[Nn];
__device__ int2  g_epk[Ee];          // (src, weight-bits)
__device__ int   g_bsum[SCB];

__device__ __align__(256) float g_t1[Nn * Hd];
__device__ __align__(256) float g_t2[Nn * Hd];
__device__ __align__(256) float g_t3[Nn * Hd];
__device__ __align__(256) float g_out[Nn * Hd];

// fp16 mirrors of p1,p2,p3 (GEMM A-operands for kt>=8)
__device__ __align__(256) __half g_m1[Nn * Hd];
__device__ __align__(256) __half g_m2[Nn * Hd];
__device__ __align__(256) __half g_m3[Nn * Hd];

// pre-packed fp16 combined weights in Bs[kt][kpair][col] layout
__device__ __align__(256) uint32_t g_wh[3][32 * 8 * 128];

__device__ float g_s1[Nn * 3];
__device__ float g_s2[Nn * 3];
__device__ float g_s3[Nn * 3];

__device__ float g_part [PMAX * Hd];
__device__ float g_part2[PMAX * Hd];
__device__ float g_scale[Hd];
__device__ float g_shift[Hd];

// ---------------- helpers ----------------
__device__ __forceinline__ void mma_f16(float* c, const uint32_t* a, const uint32_t* b) {
    asm volatile(
        "mma.sync.aligned.m16n8k16.row.col.f32.f16.f16.f32 "
        "{%0,%1,%2,%3}, {%4,%5,%6,%7}, {%8,%9}, {%0,%1,%2,%3};"
        : "+f"(c[0]), "+f"(c[1]), "+f"(c[2]), "+f"(c[3])
        : "r"(a[0]), "r"(a[1]), "r"(a[2]), "r"(a[3]), "r"(b[0]), "r"(b[1]));
}
__device__ __forceinline__ uint32_t pack_h2(float a, float b) {
    __half2 h = __floats2half2_rn(a, b);
    return *(uint32_t*)&h;
}

// ---------------- graph build ----------------
__global__ void k_init() {
    int i = blockIdx.x * blockDim.x + threadIdx.x;
    if (i < Nn) { g_deg[i] = 0; g_cnt[i] = 0; }
}

__global__ void k_count(const int* __restrict__ ei) {
    int e = blockIdx.x * blockDim.x + threadIdx.x;
    if (e < Ee) {
        int s = ei[e];
        int d = ei[e + Ee];
        if ((unsigned)s < Nn) atomicAdd(&g_deg[s], 1);
        if ((unsigned)d < Nn) atomicAdd(&g_cnt[d], 1);
    }
}

__global__ void k_scan1() {
    __shared__ int sd[1024];
    int b = blockIdx.x, tid = threadIdx.x;
    int i = b * 1024 + tid;
    int v = (i < Nn) ? g_cnt[i] : 0;
    sd[tid] = v;
    __syncthreads();
    for (int off = 1; off < 1024; off <<= 1) {
        int t = (tid >= off) ? sd[tid - off] : 0;
        __syncthreads();
        sd[tid] += t;
        __syncthreads();
    }
    if (i < Nn) g_rowptr[i + 1] = sd[tid];
    if (tid == 1023) g_bsum[b] = sd[1023];
}

// scan finalize + dinv; folds the (<=49)-element block-sum prefix in-kernel.
// blockDim=256 and 256 | 1024, so each block maps to exactly one scan1 chunk.
__global__ void k_scan3() {
    __shared__ int spart[2];
    __shared__ int soff;
    int t = threadIdx.x;
    int chunk = (int)((blockIdx.x * 256u) >> 10);
    // prefix of g_bsum[0..chunk) using first 2 warps
    if (t < 64) {
        int v = (t < chunk) ? g_bsum[t] : 0;
        #pragma unroll
        for (int off = 16; off; off >>= 1)
            v += __shfl_xor_sync(0xffffffffu, v, off);
        if ((t & 31) == 0) spart[t >> 5] = v;
    }
    __syncthreads();
    if (t == 0) soff = spart[0] + spart[1];
    __syncthreads();
    int off = soff;
    int i = blockIdx.x * 256 + t;
    if (i < Nn) {
        int r = g_rowptr[i + 1] + off;
        g_rowptr[i + 1] = r;
        g_tmpptr[i] = r - g_cnt[i];
        int d = g_deg[i];
        g_dinv[i] = (d > 0) ? rsqrtf((float)d) : 0.0f;
    }
    if (blockIdx.x == 0 && t == 0) g_rowptr[0] = 0;
}

__global__ void k_fill(const int* __restrict__ ei) {
    int e = blockIdx.x * blockDim.x + threadIdx.x;
    if (e < Ee) {
        int s = ei[e];
        int d = ei[e + Ee];
        if ((unsigned)s >= Nn || (unsigned)d >= Nn) return;
        int p = atomicAdd(&g_tmpptr[d], 1);
        float w = -g_dinv[s] * g_dinv[d];
        g_epk[p] = make_int2(s, __float_as_int(w));
    }
}

// pre-pack COMBINED weights for all 3 layers in one launch.
// Monomial basis: block0: W0 - W2, block1: W1 - 3W3, block2: 2W2, block3: 4W3
__global__ void k_wpack3(const float* __restrict__ Wa, const float* __restrict__ Wb_,
                         const float* __restrict__ Wc, uint32_t* __restrict__ out) {
    int gidx = blockIdx.x * blockDim.x + threadIdx.x;
    const int WPW = 32 * 8 * 128;
    if (gidx >= 3 * WPW) return;
    int layer = gidx / WPW;
    int idx   = gidx - layer * WPW;
    const float* W = (layer == 0) ? Wa : (layer == 1) ? Wb_ : Wc;
    int col = idx & 127;
    int kp  = (idx >> 7) & 7;
    int kt  = idx >> 10;
    int blk = kt >> 3;
    int k0  = (kt & 7) * 16 + 2 * kp;
    float a0, a1;
    const float* Wb = W + blk * 128 * Hd;
    if (blk == 0) {
        const float* W2b = W + 2 * 128 * Hd;
        a0 = Wb[k0 * Hd + col]       - W2b[k0 * Hd + col];
        a1 = Wb[(k0 + 1) * Hd + col] - W2b[(k0 + 1) * Hd + col];
    } else if (blk == 1) {
        const float* W3b = W + 3 * 128 * Hd;
        a0 = Wb[k0 * Hd + col]       - 3.f * W3b[k0 * Hd + col];
        a1 = Wb[(k0 + 1) * Hd + col] - 3.f * W3b[(k0 + 1) * Hd + col];
    } else if (blk == 2) {
        a0 = 2.f * Wb[k0 * Hd + col];
        a1 = 2.f * Wb[(k0 + 1) * Hd + col];
    } else {
        a0 = 4.f * Wb[k0 * Hd + col];
        a1 = 4.f * Wb[(k0 + 1) * Hd + col];
    }
    out[gidx] = pack_h2(a0, a1);
}

// ---------------- propagation ----------------
// layer-1 (F=3) props stay in Chebyshev form (cheap)
__global__ void k_prop3(const float* __restrict__ hin,
                        const float* __restrict__ sub,
                        float* __restrict__ out) {
    int v = blockIdx.x * blockDim.x + threadIdx.x;
    if (v >= Nn) return;
    float a0 = 0.f, a1 = 0.f, a2 = 0.f;
    int b = g_rowptr[v], en = g_rowptr[v + 1];
    for (int i = b; i < en; i++) {
        int2 e = g_epk[i];
        float w = __int_as_float(e.y);
        const float* hp = hin + e.x * 3;
        a0 += w * hp[0]; a1 += w * hp[1]; a2 += w * hp[2];
    }
    float* o = out + v * 3;
    if (sub) {
        const float* sv = sub + v * 3;
        o[0] = 2.f * a0 - sv[0]; o[1] = 2.f * a1 - sv[1]; o[2] = 2.f * a2 - sv[2];
    } else {
        o[0] = a0; o[1] = a1; o[2] = a2;
    }
}

// warp per node, monomial basis: pure gather (+ optional analytic BN on input).
// Dual-stores fp32 result + fp16 mirror (GEMM A-operand).
__global__ void k_prop128(const float* __restrict__ hin,
                          float* __restrict__ out,
                          __half* __restrict__ out16,
                          const float* __restrict__ sc,
                          const float* __restrict__ sh,
                          int bn) {
    int v = blockIdx.x * 4 + (threadIdx.x >> 5);
    if (v >= Nn) return;
    int lane = threadIdx.x & 31;
    float4 sc4, sh4;
    if (bn) {
        sc4 = ((const float4*)sc)[lane];
        sh4 = ((const float4*)sh)[lane];
    }
    int b = g_rowptr[v], en = g_rowptr[v + 1];
    float4 acc = make_float4(0.f, 0.f, 0.f, 0.f);
    float wsum = 0.f;
    int i = b;
    for (; i + 1 < en; i += 2) {
        int2 e0 = g_epk[i];
        int2 e1 = g_epk[i + 1];
        float w0 = __int_as_float(e0.y);
        float w1 = __int_as_float(e1.y);
        float4 v0 = *(const float4*)(hin + e0.x * Hd + lane * 4);
        float4 v1 = *(const float4*)(hin + e1.x * Hd + lane * 4);
        acc.x += w0 * v0.x + w1 * v1.x;
        acc.y += w0 * v0.y + w1 * v1.y;
        acc.z += w0 * v0.z + w1 * v1.z;
        acc.w += w0 * v0.w + w1 * v1.w;
        wsum += w0 + w1;
    }
    if (i < en) {
        int2 e = g_epk[i];
        float w = __int_as_float(e.y);
        float4 g = *(const float4*)(hin + e.x * Hd + lane * 4);
        acc.x += w * g.x; acc.y += w * g.y; acc.z += w * g.z; acc.w += w * g.w;
        wsum += w;
    }
    float4 r;
    if (bn) {
        r.x = sc4.x * acc.x + sh4.x * wsum;
        r.y = sc4.y * acc.y + sh4.y * wsum;
        r.z = sc4.z * acc.z + sh4.z * wsum;
        r.w = sc4.w * acc.w + sh4.w * wsum;
    } else {
        r = acc;
    }
    *(float4*)(out + v * Hd + lane * 4) = r;
    uint2 pk;
    pk.x = pack_h2(r.x, r.y);
    pk.y = pack_h2(r.z, r.w);
    *(uint2*)(out16 + v * Hd + lane * 4) = pk;
}

// ---------------- layer 1 GEMM: K=12 (+ fused stats partials) ----------------
__global__ void k_gemm12(const float* __restrict__ x,  const float* __restrict__ t1,
                         const float* __restrict__ t2, const float* __restrict__ t3,
                         const float* __restrict__ W,  const float* __restrict__ bias,
                         float* __restrict__ out) {
    __shared__ float sW[12 * Hd];
    int c = threadIdx.x;
    #pragma unroll
    for (int j = 0; j < 12; j++) sW[j * Hd + c] = W[j * Hd + c];
    __syncthreads();
    const int RPB = 32;
    int v0 = blockIdx.x * RPB;
    float bv = bias[c];
    float s = 0.f, s2 = 0.f;
    for (int r = 0; r < RPB; r++) {
        int v = v0 + r;
        if (v >= Nn) break;
        float a[12];
        #pragma unroll
        for (int f = 0; f < 3; f++) {
            a[f]     = x [v * 3 + f];
            a[3 + f] = t1[v * 3 + f];
            a[6 + f] = t2[v * 3 + f];
            a[9 + f] = t3[v * 3 + f];
        }
        float acc = bv;
        #pragma unroll
        for (int j = 0; j < 12; j++) acc += a[j] * sW[j * Hd + c];
        acc = (acc > 0.f) ? acc : 0.01f * acc;   // leaky relu
        out[v * Hd + c] = acc;
        s += acc; s2 += acc * acc;
    }
    g_part [blockIdx.x * Hd + c] = s;
    g_part2[blockIdx.x * Hd + c] = s2;
}

// ---------------- tensor-core GEMM (fp16 m16n8k16, 2-stage pipeline) --------
// A = [h(fp32,BN-fused), m1, m2, m3(fp16 mirrors)], B pre-packed weights.
// mode: 1 = leaky+stats, 2 = relu+stats, 0 = no-act + row-L2-normalize
#define BM 128
#define BK 16
#define ASTR2 12
#define BSTR2 136

__global__ __launch_bounds__(256, 2)
void k_gemm_mma(const float* __restrict__ A0,
                const __half* __restrict__ M1, const __half* __restrict__ M2,
                const __half* __restrict__ M3,
                const uint32_t* __restrict__ Wp, const float* __restrict__ bias,
                float* __restrict__ out,
                const float* __restrict__ scA, const float* __restrict__ shA,
                int mode) {
    __shared__ uint32_t As[2][BM][ASTR2];
    __shared__ uint32_t Bs[2][8][BSTR2];
    __shared__ float sred [8][64];
    __shared__ float sred2[8][64];
    __shared__ float rows2[2][BM];
    const __half* Mbuf[3] = {M1, M2, M3};

    int tid = threadIdx.x;
    int wid = tid >> 5;
    int lane = tid & 31;
    int grp = lane >> 2;
    int tig = lane & 3;
    int m_base = (wid >> 1) * 32;
    int n_base = (wid & 1) * 64;
    int row0 = blockIdx.x * BM;

    float c[2][8][4];
    #pragma unroll
    for (int mi = 0; mi < 2; mi++)
        #pragma unroll
        for (int ni = 0; ni < 8; ni++)
            #pragma unroll
            for (int q = 0; q < 4; q++) c[mi][ni][q] = 0.f;

    int la_r  = tid >> 1;
    int la_c4 = (tid & 1) * 8;       // element offset (floats or halves)
    int lb_k  = tid >> 5;
    int lb_c4 = (tid & 31) * 4;

    auto load_stage = [&](int kt, uint4& ua, uint4& ub) {
        int cb = (kt & 7) * BK;
        int gr = row0 + la_r;
        if (kt >= 8) {
            // fp16 mirror: single 16B load, no conversion
            ua = (gr < Nn)
               ? *(const uint4*)(Mbuf[(kt >> 3) - 1] + gr * Hd + cb + la_c4)
               : make_uint4(0u, 0u, 0u, 0u);
        } else {
            // h (fp32) with analytic BN fused
            float4 v0 = make_float4(0.f,0.f,0.f,0.f), v1 = v0;
            if (gr < Nn) {
                const float4* src = (const float4*)(A0 + gr * Hd + cb + la_c4);
                v0 = src[0]; v1 = src[1];
            }
            float4 s0 = *(const float4*)(scA + cb + la_c4);
            float4 s1 = *(const float4*)(scA + cb + la_c4 + 4);
            float4 h0 = *(const float4*)(shA + cb + la_c4);
            float4 h1 = *(const float4*)(shA + cb + la_c4 + 4);
            v0.x = v0.x * s0.x + h0.x; v0.y = v0.y * s0.y + h0.y;
            v0.z = v0.z * s0.z + h0.z; v0.w = v0.w * s0.w + h0.w;
            v1.x = v1.x * s1.x + h1.x; v1.y = v1.y * s1.y + h1.y;
            v1.z = v1.z * s1.z + h1.z; v1.w = v1.w * s1.w + h1.w;
            if (gr >= Nn) { v0 = make_float4(0,0,0,0); v1 = v0; }
            ua.x = pack_h2(v0.x, v0.y);
            ua.y = pack_h2(v0.z, v0.w);
            ua.z = pack_h2(v1.x, v1.y);
            ua.w = pack_h2(v1.z, v1.w);
        }
        ub = *(const uint4*)(Wp + kt * 1024 + lb_k * 128 + lb_c4);
    };

    {
        uint4 ua, ub;
        load_stage(0, ua, ub);
        *(uint4*)&As[0][la_r][la_c4 >> 1] = ua;
        *(uint4*)&Bs[0][lb_k][lb_c4] = ub;
    }
    __syncthreads();

    for (int kt = 0; kt < 32; kt++) {
        int cur = kt & 1, nxt = cur ^ 1;
        uint4 na, nb;
        if (kt < 31) load_stage(kt + 1, na, nb);
        {
            uint32_t a[2][4], b[8][2];
            #pragma unroll
            for (int mi = 0; mi < 2; mi++) {
                int m0 = m_base + mi * 16 + grp;
                a[mi][0] = As[cur][m0][tig];
                a[mi][1] = As[cur][m0 + 8][tig];
                a[mi][2] = As[cur][m0][tig + 4];
                a[mi][3] = As[cur][m0 + 8][tig + 4];
            }
            #pragma unroll
            for (int ni = 0; ni < 8; ni++) {
                int nc = n_base + ni * 8 + grp;
                b[ni][0] = Bs[cur][tig][nc];
                b[ni][1] = Bs[cur][tig + 4][nc];
            }
            #pragma unroll
            for (int mi = 0; mi < 2; mi++)
                #pragma unroll
                for (int ni = 0; ni < 8; ni++)
                    mma_f16(c[mi][ni], a[mi], b[ni]);
        }
        if (kt < 31) {
            *(uint4*)&As[nxt][la_r][la_c4 >> 1] = na;
            *(uint4*)&Bs[nxt][lb_k][lb_c4] = nb;
        }
        __syncthreads();
    }

    // ---- bias + activation (zero invalid rows) ----
    #pragma unroll
    for (int mi = 0; mi < 2; mi++) {
        #pragma unroll
        for (int half = 0; half < 2; half++) {
            int row = row0 + m_base + mi * 16 + grp + half * 8;
            bool valid = row < Nn;
            #pragma unroll
            for (int ni = 0; ni < 8; ni++) {
                #pragma unroll
                for (int par = 0; par < 2; par++) {
                    int q = half * 2 + par;
                    int col = n_base + ni * 8 + tig * 2 + par;
                    float f = c[mi][ni][q] + __ldg(bias + col);
                    if (mode == 1)      f = (f > 0.f) ? f : 0.01f * f;
                    else if (mode == 2) f = fmaxf(f, 0.f);
                    c[mi][ni][q] = valid ? f : 0.f;
                }
            }
        }
    }

    float rscale[2][2] = {{1.f,1.f},{1.f,1.f}};

    if (mode != 0) {
        float ls[8][2], ls2[8][2];
        #pragma unroll
        for (int ni = 0; ni < 8; ni++)
            #pragma unroll
            for (int par = 0; par < 2; par++) {
                float s = 0.f, s2 = 0.f;
                #pragma unroll
                for (int mi = 0; mi < 2; mi++)
                    #pragma unroll
                    for (int half = 0; half < 2; half++) {
                        float f = c[mi][ni][half * 2 + par];
                        s += f; s2 += f * f;
                    }
                ls[ni][par] = s; ls2[ni][par] = s2;
            }
        #pragma unroll
        for (int off = 4; off < 32; off <<= 1) {
            #pragma unroll
            for (int ni = 0; ni < 8; ni++)
                #pragma unroll
                for (int par = 0; par < 2; par++) {
                    ls [ni][par] += __shfl_xor_sync(0xffffffffu, ls [ni][par], off);
                    ls2[ni][par] += __shfl_xor_sync(0xffffffffu, ls2[ni][par], off);
                }
        }
        if (lane < 4) {
            #pragma unroll
            for (int ni = 0; ni < 8; ni++)
                #pragma unroll
                for (int par = 0; par < 2; par++) {
                    sred [wid][ni * 8 + tig * 2 + par] = ls [ni][par];
                    sred2[wid][ni * 8 + tig * 2 + par] = ls2[ni][par];
                }
        }
        __syncthreads();
        if (tid < Hd) {
            int hf = tid >> 6, cl = tid & 63;
            float s = 0.f, s2 = 0.f;
            #pragma unroll
            for (int j = 0; j < 4; j++) {
                s  += sred [2 * j + hf][cl];
                s2 += sred2[2 * j + hf][cl];
            }
            g_part [blockIdx.x * Hd + tid] = s;
            g_part2[blockIdx.x * Hd + tid] = s2;
        }
    } else {
        #pragma unroll
        for (int mi = 0; mi < 2; mi++)
            #pragma unroll
            for (int half = 0; half < 2; half++) {
                float rsq = 0.f;
                #pragma unroll
                for (int ni = 0; ni < 8; ni++) {
                    float f0 = c[mi][ni][half * 2 + 0];
                    float f1 = c[mi][ni][half * 2 + 1];
                    rsq += f0 * f0 + f1 * f1;
                }
                rsq += __shfl_xor_sync(0xffffffffu, rsq, 1);
                rsq += __shfl_xor_sync(0xffffffffu, rsq, 2);
                if (tig == 0)
                    rows2[wid & 1][m_base + mi * 16 + grp + half * 8] = rsq;
            }
        __syncthreads();
        #pragma unroll
        for (int mi = 0; mi < 2; mi++)
            #pragma unroll
            for (int half = 0; half < 2; half++) {
                int rl = m_base + mi * 16 + grp + half * 8;
                float tot = rows2[0][rl] + rows2[1][rl];
                rscale[mi][half] = 1.f / fmaxf(sqrtf(tot), 1e-12f);
            }
    }

    // ---- store ----
    #pragma unroll
    for (int mi = 0; mi < 2; mi++) {
        #pragma unroll
        for (int half = 0; half < 2; half++) {
            int row = row0 + m_base + mi * 16 + grp + half * 8;
            if (row < Nn) {
                float rs = rscale[mi][half];
                #pragma unroll
                for (int ni = 0; ni < 8; ni++) {
                    int col = n_base + ni * 8 + tig * 2;
                    float f0 = c[mi][ni][half * 2 + 0] * rs;
                    float f1 = c[mi][ni][half * 2 + 1] * rs;
                    *(float2*)(out + row * Hd + col) = make_float2(f0, f1);
                }
            }
        }
    }
}

// ---------------- BN finalize (parallel: one block per channel) -------------
__global__ void k_bnfin(const float* __restrict__ gamma, const float* __restrict__ beta,
                        int nb) {
    int c = blockIdx.x;
    int t = threadIdx.x;
    float s = 0.f, s2 = 0.f;
    for (int b = t; b < nb; b += 256) {
        s  += g_part [b * Hd + c];
        s2 += g_part2[b * Hd + c];
    }
    __shared__ float ss[256], ss2[256];
    ss[t] = s; ss2[t] = s2;
    __syncthreads();
    #pragma unroll
    for (int off = 128; off; off >>= 1) {
        if (t < off) { ss[t] += ss[t + off]; ss2[t] += ss2[t + off]; }
        __syncthreads();
    }
    if (t == 0) {
        float m   = ss[0] / (float)Nn;
        float var = ss2[0] / (float)Nn - m * m;
        float inv = rsqrtf(var + 1e-5f);
        float sc  = gamma[c] * inv;
        g_scale[c] = sc;
        g_shift[c] = beta[c] - m * sc;
    }
}

// ---------------- host ----------------
extern "C" void kernel_launch(void* const* d_in, const int* in_sizes, int n_in,
                              void* d_out, int out_size) {
    const float* x  = (const float*)d_in[0];
    const int*   ei = (const int*)d_in[1];   // int32 (JAX x64 disabled)
    const float* W1 = (const float*)d_in[2];  const float* b1 = (const float*)d_in[3];
    const float* W2 = (const float*)d_in[4];  const float* b2 = (const float*)d_in[5];
    const float* W3 = (const float*)d_in[6];  const float* b3 = (const float*)d_in[7];
    const float* W4 = (const float*)d_in[8];  const float* b4 = (const float*)d_in[9];
    const float* g1 = (const float*)d_in[10]; const float* be1 = (const float*)d_in[11];
    const float* g2 = (const float*)d_in[12]; const float* be2 = (const float*)d_in[13];
    const float* g3 = (const float*)d_in[14]; const float* be3 = (const float*)d_in[15];

    float *p_t1, *p_t2, *p_t3, *p_out, *p_s1, *p_s2, *p_s3, *p_sc, *p_sh;
    __half *p_m1, *p_m2, *p_m3;
    uint32_t* p_wh;
    cudaGetSymbolAddress((void**)&p_t1,  g_t1);
    cudaGetSymbolAddress((void**)&p_t2,  g_t2);
    cudaGetSymbolAddress((void**)&p_t3,  g_t3);
    cudaGetSymbolAddress((void**)&p_out, g_out);
    cudaGetSymbolAddress((void**)&p_s1,  g_s1);
    cudaGetSymbolAddress((void**)&p_s2,  g_s2);
    cudaGetSymbolAddress((void**)&p_s3,  g_s3);
    cudaGetSymbolAddress((void**)&p_sc,  g_scale);
    cudaGetSymbolAddress((void**)&p_sh,  g_shift);
    cudaGetSymbolAddress((void**)&p_m1,  g_m1);
    cudaGetSymbolAddress((void**)&p_m2,  g_m2);
    cudaGetSymbolAddress((void**)&p_m3,  g_m3);
    cudaGetSymbolAddress((void**)&p_wh,  g_wh);

    const int TB = 256;
    const int WPW = 32 * 8 * 128;
    // graph build
    k_init <<<(Nn + TB - 1) / TB, TB>>>();
    k_count<<<(Ee + TB - 1) / TB, TB>>>(ei);
    k_scan1<<<SCB, 1024>>>();
    k_scan3<<<(Nn + TB - 1) / TB, TB>>>();
    k_fill <<<(Ee + TB - 1) / TB, TB>>>(ei);

    // pre-pack combined (monomial-basis) weights for all layers, one launch
    k_wpack3<<<(3 * WPW + TB - 1) / TB, TB>>>(W2, W3, W4, p_wh);

    int gP128 = (Nn + 3) / 4;
    int gGemm = (Nn + BM - 1) / BM;      // 391
    int g12   = (Nn + 31) / 32;          // 1563

    // layer 1 (F=3, Chebyshev form)
    k_prop3<<<(Nn + TB - 1) / TB, TB>>>(x, nullptr, p_s1);
    k_prop3<<<(Nn + TB - 1) / TB, TB>>>(p_s1, x, p_s2);
    k_prop3<<<(Nn + TB - 1) / TB, TB>>>(p_s2, p_s1, p_s3);
    k_gemm12<<<g12, Hd>>>(x, p_s1, p_s2, p_s3, W1, b1, p_out);
    k_bnfin<<<Hd, 256>>>(g1, be1, g12);

    // layer 2: p1 = L(bn(h)), p2 = L p1, p3 = L p2 (pure gathers + mirrors)
    k_prop128<<<gP128, 128>>>(p_out, p_t1, p_m1, p_sc, p_sh, 1);
    k_prop128<<<gP128, 128>>>(p_t1, p_t2, p_m2, nullptr, nullptr, 0);
    k_prop128<<<gP128, 128>>>(p_t2, p_t3, p_m3, nullptr, nullptr, 0);
    k_gemm_mma<<<gGemm, 256>>>(p_out, p_m1, p_m2, p_m3, p_wh + 0 * WPW, b2, p_out, p_sc, p_sh, 1);
    k_bnfin<<<Hd, 256>>>(g2, be2, gGemm);

    // layer 3
    k_prop128<<<gP128, 128>>>(p_out, p_t1, p_m1, p_sc, p_sh, 1);
    k_prop128<<<gP128, 128>>>(p_t1, p_t2, p_m2, nullptr, nullptr, 0);
    k_prop128<<<gP128, 128>>>(p_t2, p_t3, p_m3, nullptr, nullptr, 0);
    k_gemm_mma<<<gGemm, 256>>>(p_out, p_m1, p_m2, p_m3, p_wh + 1 * WPW, b3, p_out, p_sc, p_sh, 2);
    k_bnfin<<<Hd, 256>>>(g3, be3, gGemm);

    // layer 4: props + GEMM with fused row-normalize, straight to d_out
    k_prop128<<<gP128, 128>>>(p_out, p_t1, p_m1, p_sc, p_sh, 1);
    k_prop128<<<gP128, 128>>>(p_t1, p_t2, p_m2, nullptr, nullptr, 0);
    k_prop128<<<gP128, 128>>>(p_t2, p_t3, p_m3, nullptr, nullptr, 0);
    k_gemm_mma<<<gGemm, 256>>>(p_out, p_m1, p_m2, p_m3, p_wh + 2 * WPW, b4, (float*)d_out,
                               p_sc, p_sh, 0);
}

// round 17
// speedup vs baseline: 1.3672x; 1.0149x over previous
#include <cuda_runtime.h>
#include <cuda_bf16.h>
#include <cuda_fp16.h>
#include <cstdint>

#define Nn 50000
#define Ee 800000
#define Hd 128
#define SCB 49       // scan blocks (ceil(Nn/1024))
#define PMAX 1600    // max stats-partial blocks (gemm12 uses 1563)

// ---------------- scratch ----------------
__device__ int   g_deg[Nn];
__device__ int   g_cnt[Nn];
__device__ int   g_rowptr[Nn + 1];
__device__ int   g_tmpptr[Nn];
__device__ float g_dinv[Nn];
__device__ int2  g_epk[Ee];          // (src, weight-bits)
__device__ int   g_bsum[SCB];

__device__ __align__(256) float g_t1[Nn * Hd];
__device__ __align__(256) float g_t2[Nn * Hd];
__device__ __align__(256) float g_out[Nn * Hd];

// fp16 mirrors of p1,p2,p3 (GEMM A-operands for kt>=8)
__device__ __align__(256) __half g_m1[Nn * Hd];
__device__ __align__(256) __half g_m2[Nn * Hd];
__device__ __align__(256) __half g_m3[Nn * Hd];

// pre-packed fp16 combined weights in Bs[kt][kpair][col] layout
__device__ __align__(256) uint32_t g_wh[3][32 * 8 * 128];

__device__ float g_s1[Nn * 3];
__device__ float g_s2[Nn * 3];
__device__ float g_s3[Nn * 3];

__device__ float g_part [PMAX * Hd];
__device__ float g_part2[PMAX * Hd];
__device__ float g_scale[Hd];
__device__ float g_shift[Hd];

// ---------------- helpers ----------------
__device__ __forceinline__ void mma_f16(float* c, const uint32_t* a, const uint32_t* b) {
    asm volatile(
        "mma.sync.aligned.m16n8k16.row.col.f32.f16.f16.f32 "
        "{%0,%1,%2,%3}, {%4,%5,%6,%7}, {%8,%9}, {%0,%1,%2,%3};"
        : "+f"(c[0]), "+f"(c[1]), "+f"(c[2]), "+f"(c[3])
        : "r"(a[0]), "r"(a[1]), "r"(a[2]), "r"(a[3]), "r"(b[0]), "r"(b[1]));
}
__device__ __forceinline__ uint32_t pack_h2(float a, float b) {
    __half2 h = __floats2half2_rn(a, b);
    return *(uint32_t*)&h;
}

// ---------------- graph build ----------------
__global__ void k_init() {
    int i = blockIdx.x * blockDim.x + threadIdx.x;
    if (i < Nn) { g_deg[i] = 0; g_cnt[i] = 0; }
}

__global__ void k_count(const int* __restrict__ ei) {
    int e = blockIdx.x * blockDim.x + threadIdx.x;
    if (e < Ee) {
        int s = ei[e];
        int d = ei[e + Ee];
        if ((unsigned)s < Nn) atomicAdd(&g_deg[s], 1);
        if ((unsigned)d < Nn) atomicAdd(&g_cnt[d], 1);
    }
}

__global__ void k_scan1() {
    __shared__ int sd[1024];
    int b = blockIdx.x, tid = threadIdx.x;
    int i = b * 1024 + tid;
    int v = (i < Nn) ? g_cnt[i] : 0;
    sd[tid] = v;
    __syncthreads();
    for (int off = 1; off < 1024; off <<= 1) {
        int t = (tid >= off) ? sd[tid - off] : 0;
        __syncthreads();
        sd[tid] += t;
        __syncthreads();
    }
    if (i < Nn) g_rowptr[i + 1] = sd[tid];
    if (tid == 1023) g_bsum[b] = sd[1023];
}

// scan finalize + dinv; folds the (<=49)-element block-sum prefix in-kernel.
__global__ void k_scan3() {
    __shared__ int spart[2];
    __shared__ int soff;
    int t = threadIdx.x;
    int chunk = (int)((blockIdx.x * 256u) >> 10);
    if (t < 64) {
        int v = (t < chunk) ? g_bsum[t] : 0;
        #pragma unroll
        for (int off = 16; off; off >>= 1)
            v += __shfl_xor_sync(0xffffffffu, v, off);
        if ((t & 31) == 0) spart[t >> 5] = v;
    }
    __syncthreads();
    if (t == 0) soff = spart[0] + spart[1];
    __syncthreads();
    int off = soff;
    int i = blockIdx.x * 256 + t;
    if (i < Nn) {
        int r = g_rowptr[i + 1] + off;
        g_rowptr[i + 1] = r;
        g_tmpptr[i] = r - g_cnt[i];
        int d = g_deg[i];
        g_dinv[i] = (d > 0) ? rsqrtf((float)d) : 0.0f;
    }
    if (blockIdx.x == 0 && t == 0) g_rowptr[0] = 0;
}

__global__ void k_fill(const int* __restrict__ ei) {
    int e = blockIdx.x * blockDim.x + threadIdx.x;
    if (e < Ee) {
        int s = ei[e];
        int d = ei[e + Ee];
        if ((unsigned)s >= Nn || (unsigned)d >= Nn) return;
        int p = atomicAdd(&g_tmpptr[d], 1);
        float w = -g_dinv[s] * g_dinv[d];
        g_epk[p] = make_int2(s, __float_as_int(w));
    }
}

// pre-pack COMBINED weights for all 3 layers in one launch.
// Monomial basis: block0: W0 - W2, block1: W1 - 3W3, block2: 2W2, block3: 4W3
__global__ void k_wpack3(const float* __restrict__ Wa, const float* __restrict__ Wb_,
                         const float* __restrict__ Wc, uint32_t* __restrict__ out) {
    int gidx = blockIdx.x * blockDim.x + threadIdx.x;
    const int WPW = 32 * 8 * 128;
    if (gidx >= 3 * WPW) return;
    int layer = gidx / WPW;
    int idx   = gidx - layer * WPW;
    const float* W = (layer == 0) ? Wa : (layer == 1) ? Wb_ : Wc;
    int col = idx & 127;
    int kp  = (idx >> 7) & 7;
    int kt  = idx >> 10;
    int blk = kt >> 3;
    int k0  = (kt & 7) * 16 + 2 * kp;
    float a0, a1;
    const float* Wb = W + blk * 128 * Hd;
    if (blk == 0) {
        const float* W2b = W + 2 * 128 * Hd;
        a0 = Wb[k0 * Hd + col]       - W2b[k0 * Hd + col];
        a1 = Wb[(k0 + 1) * Hd + col] - W2b[(k0 + 1) * Hd + col];
    } else if (blk == 1) {
        const float* W3b = W + 3 * 128 * Hd;
        a0 = Wb[k0 * Hd + col]       - 3.f * W3b[k0 * Hd + col];
        a1 = Wb[(k0 + 1) * Hd + col] - 3.f * W3b[(k0 + 1) * Hd + col];
    } else if (blk == 2) {
        a0 = 2.f * Wb[k0 * Hd + col];
        a1 = 2.f * Wb[(k0 + 1) * Hd + col];
    } else {
        a0 = 4.f * Wb[k0 * Hd + col];
        a1 = 4.f * Wb[(k0 + 1) * Hd + col];
    }
    out[gidx] = pack_h2(a0, a1);
}

// ---------------- propagation ----------------
// layer-1 (F=3) props stay in Chebyshev form (cheap)
__global__ void k_prop3(const float* __restrict__ hin,
                        const float* __restrict__ sub,
                        float* __restrict__ out) {
    int v = blockIdx.x * blockDim.x + threadIdx.x;
    if (v >= Nn) return;
    float a0 = 0.f, a1 = 0.f, a2 = 0.f;
    int b = g_rowptr[v], en = g_rowptr[v + 1];
    for (int i = b; i < en; i++) {
        int2 e = g_epk[i];
        float w = __int_as_float(e.y);
        const float* hp = hin + e.x * 3;
        a0 += w * hp[0]; a1 += w * hp[1]; a2 += w * hp[2];
    }
    float* o = out + v * 3;
    if (sub) {
        const float* sv = sub + v * 3;
        o[0] = 2.f * a0 - sv[0]; o[1] = 2.f * a1 - sv[1]; o[2] = 2.f * a2 - sv[2];
    } else {
        o[0] = a0; o[1] = a1; o[2] = a2;
    }
}

// warp per node, monomial basis: pure gather (+ optional analytic BN on input).
// Dual-stores fp32 (optional, out may be null) + fp16 mirror.
__global__ void k_prop128(const float* __restrict__ hin,
                          float* __restrict__ out,
                          __half* __restrict__ out16,
                          const float* __restrict__ sc,
                          const float* __restrict__ sh,
                          int bn) {
    int v = blockIdx.x * 4 + (threadIdx.x >> 5);
    if (v >= Nn) return;
    int lane = threadIdx.x & 31;
    float4 sc4, sh4;
    if (bn) {
        sc4 = ((const float4*)sc)[lane];
        sh4 = ((const float4*)sh)[lane];
    }
    int b = g_rowptr[v], en = g_rowptr[v + 1];
    float4 acc = make_float4(0.f, 0.f, 0.f, 0.f);
    float wsum = 0.f;
    int i = b;
    for (; i + 1 < en; i += 2) {
        int2 e0 = g_epk[i];
        int2 e1 = g_epk[i + 1];
        float w0 = __int_as_float(e0.y);
        float w1 = __int_as_float(e1.y);
        float4 v0 = *(const float4*)(hin + e0.x * Hd + lane * 4);
        float4 v1 = *(const float4*)(hin + e1.x * Hd + lane * 4);
        acc.x += w0 * v0.x + w1 * v1.x;
        acc.y += w0 * v0.y + w1 * v1.y;
        acc.z += w0 * v0.z + w1 * v1.z;
        acc.w += w0 * v0.w + w1 * v1.w;
        wsum += w0 + w1;
    }
    if (i < en) {
        int2 e = g_epk[i];
        float w = __int_as_float(e.y);
        float4 g = *(const float4*)(hin + e.x * Hd + lane * 4);
        acc.x += w * g.x; acc.y += w * g.y; acc.z += w * g.z; acc.w += w * g.w;
        wsum += w;
    }
    float4 r;
    if (bn) {
        r.x = sc4.x * acc.x + sh4.x * wsum;
        r.y = sc4.y * acc.y + sh4.y * wsum;
        r.z = sc4.z * acc.z + sh4.z * wsum;
        r.w = sc4.w * acc.w + sh4.w * wsum;
    } else {
        r = acc;
    }
    if (out) *(float4*)(out + v * Hd + lane * 4) = r;
    uint2 pk;
    pk.x = pack_h2(r.x, r.y);
    pk.y = pack_h2(r.z, r.w);
    *(uint2*)(out16 + v * Hd + lane * 4) = pk;
}

// ---------------- layer 1 GEMM: K=12 (+ fused stats partials) ----------------
__global__ void k_gemm12(const float* __restrict__ x,  const float* __restrict__ t1,
                         const float* __restrict__ t2, const float* __restrict__ t3,
                         const float* __restrict__ W,  const float* __restrict__ bias,
                         float* __restrict__ out) {
    __shared__ float sW[12 * Hd];
    int c = threadIdx.x;
    #pragma unroll
    for (int j = 0; j < 12; j++) sW[j * Hd + c] = W[j * Hd + c];
    __syncthreads();
    const int RPB = 32;
    int v0 = blockIdx.x * RPB;
    float bv = bias[c];
    float s = 0.f, s2 = 0.f;
    for (int r = 0; r < RPB; r++) {
        int v = v0 + r;
        if (v >= Nn) break;
        float a[12];
        #pragma unroll
        for (int f = 0; f < 3; f++) {
            a[f]     = x [v * 3 + f];
            a[3 + f] = t1[v * 3 + f];
            a[6 + f] = t2[v * 3 + f];
            a[9 + f] = t3[v * 3 + f];
        }
        float acc = bv;
        #pragma unroll
        for (int j = 0; j < 12; j++) acc += a[j] * sW[j * Hd + c];
        acc = (acc > 0.f) ? acc : 0.01f * acc;   // leaky relu
        out[v * Hd + c] = acc;
        s += acc; s2 += acc * acc;
    }
    g_part [blockIdx.x * Hd + c] = s;
    g_part2[blockIdx.x * Hd + c] = s2;
}

// ---------------- tensor-core GEMM (fp16 m16n8k16, 2-stage pipeline) --------
// A = [h(fp32,BN-fused), m1, m2, m3(fp16 mirrors)], B pre-packed weights.
// mode: 1 = leaky+stats, 2 = relu+stats, 0 = no-act + row-L2-normalize
#define BM 128
#define BK 16
#define ASTR2 12
#define BSTR2 136

__global__ __launch_bounds__(256, 2)
void k_gemm_mma(const float* __restrict__ A0,
                const __half* __restrict__ M1, const __half* __restrict__ M2,
                const __half* __restrict__ M3,
                const uint32_t* __restrict__ Wp, const float* __restrict__ bias,
                float* __restrict__ out,
                const float* __restrict__ scA, const float* __restrict__ shA,
                int mode) {
    __shared__ uint32_t As[2][BM][ASTR2];
    __shared__ uint32_t Bs[2][8][BSTR2];
    __shared__ float sred [8][64];
    __shared__ float sred2[8][64];
    __shared__ float rows2[2][BM];
    const __half* Mbuf[3] = {M1, M2, M3};

    int tid = threadIdx.x;
    int wid = tid >> 5;
    int lane = tid & 31;
    int grp = lane >> 2;
    int tig = lane & 3;
    int m_base = (wid >> 1) * 32;
    int n_base = (wid & 1) * 64;
    int row0 = blockIdx.x * BM;

    float c[2][8][4];
    #pragma unroll
    for (int mi = 0; mi < 2; mi++)
        #pragma unroll
        for (int ni = 0; ni < 8; ni++)
            #pragma unroll
            for (int q = 0; q < 4; q++) c[mi][ni][q] = 0.f;

    int la_r  = tid >> 1;
    int la_c4 = (tid & 1) * 8;
    int lb_k  = tid >> 5;
    int lb_c4 = (tid & 31) * 4;

    auto load_stage = [&](int kt, uint4& ua, uint4& ub) {
        int cb = (kt & 7) * BK;
        int gr = row0 + la_r;
        if (kt >= 8) {
            ua = (gr < Nn)
               ? *(const uint4*)(Mbuf[(kt >> 3) - 1] + gr * Hd + cb + la_c4)
               : make_uint4(0u, 0u, 0u, 0u);
        } else {
            float4 v0 = make_float4(0.f,0.f,0.f,0.f), v1 = v0;
            if (gr < Nn) {
                const float4* src = (const float4*)(A0 + gr * Hd + cb + la_c4);
                v0 = src[0]; v1 = src[1];
            }
            float4 s0 = *(const float4*)(scA + cb + la_c4);
            float4 s1 = *(const float4*)(scA + cb + la_c4 + 4);
            float4 h0 = *(const float4*)(shA + cb + la_c4);
            float4 h1 = *(const float4*)(shA + cb + la_c4 + 4);
            v0.x = v0.x * s0.x + h0.x; v0.y = v0.y * s0.y + h0.y;
            v0.z = v0.z * s0.z + h0.z; v0.w = v0.w * s0.w + h0.w;
            v1.x = v1.x * s1.x + h1.x; v1.y = v1.y * s1.y + h1.y;
            v1.z = v1.z * s1.z + h1.z; v1.w = v1.w * s1.w + h1.w;
            if (gr >= Nn) { v0 = make_float4(0,0,0,0); v1 = v0; }
            ua.x = pack_h2(v0.x, v0.y);
            ua.y = pack_h2(v0.z, v0.w);
            ua.z = pack_h2(v1.x, v1.y);
            ua.w = pack_h2(v1.z, v1.w);
        }
        ub = *(const uint4*)(Wp + kt * 1024 + lb_k * 128 + lb_c4);
    };

    {
        uint4 ua, ub;
        load_stage(0, ua, ub);
        *(uint4*)&As[0][la_r][la_c4 >> 1] = ua;
        *(uint4*)&Bs[0][lb_k][lb_c4] = ub;
    }
    __syncthreads();

    for (int kt = 0; kt < 32; kt++) {
        int cur = kt & 1, nxt = cur ^ 1;
        uint4 na, nb;
        if (kt < 31) load_stage(kt + 1, na, nb);
        {
            uint32_t a[2][4], b[8][2];
            #pragma unroll
            for (int mi = 0; mi < 2; mi++) {
                int m0 = m_base + mi * 16 + grp;
                a[mi][0] = As[cur][m0][tig];
                a[mi][1] = As[cur][m0 + 8][tig];
                a[mi][2] = As[cur][m0][tig + 4];
                a[mi][3] = As[cur][m0 + 8][tig + 4];
            }
            #pragma unroll
            for (int ni = 0; ni < 8; ni++) {
                int nc = n_base + ni * 8 + grp;
                b[ni][0] = Bs[cur][tig][nc];
                b[ni][1] = Bs[cur][tig + 4][nc];
            }
            #pragma unroll
            for (int mi = 0; mi < 2; mi++)
                #pragma unroll
                for (int ni = 0; ni < 8; ni++)
                    mma_f16(c[mi][ni], a[mi], b[ni]);
        }
        if (kt < 31) {
            *(uint4*)&As[nxt][la_r][la_c4 >> 1] = na;
            *(uint4*)&Bs[nxt][lb_k][lb_c4] = nb;
        }
        __syncthreads();
    }

    // ---- bias + activation (zero invalid rows) ----
    #pragma unroll
    for (int mi = 0; mi < 2; mi++) {
        #pragma unroll
        for (int half = 0; half < 2; half++) {
            int row = row0 + m_base + mi * 16 + grp + half * 8;
            bool valid = row < Nn;
            #pragma unroll
            for (int ni = 0; ni < 8; ni++) {
                #pragma unroll
                for (int par = 0; par < 2; par++) {
                    int q = half * 2 + par;
                    int col = n_base + ni * 8 + tig * 2 + par;
                    float f = c[mi][ni][q] + __ldg(bias + col);
                    if (mode == 1)      f = (f > 0.f) ? f : 0.01f * f;
                    else if (mode == 2) f = fmaxf(f, 0.f);
                    c[mi][ni][q] = valid ? f : 0.f;
                }
            }
        }
    }

    float rscale[2][2] = {{1.f,1.f},{1.f,1.f}};

    if (mode != 0) {
        float ls[8][2], ls2[8][2];
        #pragma unroll
        for (int ni = 0; ni < 8; ni++)
            #pragma unroll
            for (int par = 0; par < 2; par++) {
                float s = 0.f, s2 = 0.f;
                #pragma unroll
                for (int mi = 0; mi < 2; mi++)
                    #pragma unroll
                    for (int half = 0; half < 2; half++) {
                        float f = c[mi][ni][half * 2 + par];
                        s += f; s2 += f * f;
                    }
                ls[ni][par] = s; ls2[ni][par] = s2;
            }
        #pragma unroll
        for (int off = 4; off < 32; off <<= 1) {
            #pragma unroll
            for (int ni = 0; ni < 8; ni++)
                #pragma unroll
                for (int par = 0; par < 2; par++) {
                    ls [ni][par] += __shfl_xor_sync(0xffffffffu, ls [ni][par], off);
                    ls2[ni][par] += __shfl_xor_sync(0xffffffffu, ls2[ni][par], off);
                }
        }
        if (lane < 4) {
            #pragma unroll
            for (int ni = 0; ni < 8; ni++)
                #pragma unroll
                for (int par = 0; par < 2; par++) {
                    sred [wid][ni * 8 + tig * 2 + par] = ls [ni][par];
                    sred2[wid][ni * 8 + tig * 2 + par] = ls2[ni][par];
                }
        }
        __syncthreads();
        if (tid < Hd) {
            int hf = tid >> 6, cl = tid & 63;
            float s = 0.f, s2 = 0.f;
            #pragma unroll
            for (int j = 0; j < 4; j++) {
                s  += sred [2 * j + hf][cl];
                s2 += sred2[2 * j + hf][cl];
            }
            g_part [blockIdx.x * Hd + tid] = s;
            g_part2[blockIdx.x * Hd + tid] = s2;
        }
    } else {
        #pragma unroll
        for (int mi = 0; mi < 2; mi++)
            #pragma unroll
            for (int half = 0; half < 2; half++) {
                float rsq = 0.f;
                #pragma unroll
                for (int ni = 0; ni < 8; ni++) {
                    float f0 = c[mi][ni][half * 2 + 0];
                    float f1 = c[mi][ni][half * 2 + 1];
                    rsq += f0 * f0 + f1 * f1;
                }
                rsq += __shfl_xor_sync(0xffffffffu, rsq, 1);
                rsq += __shfl_xor_sync(0xffffffffu, rsq, 2);
                if (tig == 0)
                    rows2[wid & 1][m_base + mi * 16 + grp + half * 8] = rsq;
            }
        __syncthreads();
        #pragma unroll
        for (int mi = 0; mi < 2; mi++)
            #pragma unroll
            for (int half = 0; half < 2; half++) {
                int rl = m_base + mi * 16 + grp + half * 8;
                float tot = rows2[0][rl] + rows2[1][rl];
                rscale[mi][half] = 1.f / fmaxf(sqrtf(tot), 1e-12f);
            }
    }

    // ---- store ----
    #pragma unroll
    for (int mi = 0; mi < 2; mi++) {
        #pragma unroll
        for (int half = 0; half < 2; half++) {
            int row = row0 + m_base + mi * 16 + grp + half * 8;
            if (row < Nn) {
                float rs = rscale[mi][half];
                #pragma unroll
                for (int ni = 0; ni < 8; ni++) {
                    int col = n_base + ni * 8 + tig * 2;
                    float f0 = c[mi][ni][half * 2 + 0] * rs;
                    float f1 = c[mi][ni][half * 2 + 1] * rs;
                    *(float2*)(out + row * Hd + col) = make_float2(f0, f1);
                }
            }
        }
    }
}

// ---------------- BN finalize (parallel: one block per channel) -------------
__global__ void k_bnfin(const float* __restrict__ gamma, const float* __restrict__ beta,
                        int nb) {
    int c = blockIdx.x;
    int t = threadIdx.x;
    float s = 0.f, s2 = 0.f;
    for (int b = t; b < nb; b += 256) {
        s  += g_part [b * Hd + c];
        s2 += g_part2[b * Hd + c];
    }
    __shared__ float ss[256], ss2[256];
    ss[t] = s; ss2[t] = s2;
    __syncthreads();
    #pragma unroll
    for (int off = 128; off; off >>= 1) {
        if (t < off) { ss[t] += ss[t + off]; ss2[t] += ss2[t + off]; }
        __syncthreads();
    }
    if (t == 0) {
        float m   = ss[0] / (float)Nn;
        float var = ss2[0] / (float)Nn - m * m;
        float inv = rsqrtf(var + 1e-5f);
        float sc  = gamma[c] * inv;
        g_scale[c] = sc;
        g_shift[c] = beta[c] - m * sc;
    }
}

// ---------------- host ----------------
extern "C" void kernel_launch(void* const* d_in, const int* in_sizes, int n_in,
                              void* d_out, int out_size) {
    const float* x  = (const float*)d_in[0];
    const int*   ei = (const int*)d_in[1];   // int32 (JAX x64 disabled)
    const float* W1 = (const float*)d_in[2];  const float* b1 = (const float*)d_in[3];
    const float* W2 = (const float*)d_in[4];  const float* b2 = (const float*)d_in[5];
    const float* W3 = (const float*)d_in[6];  const float* b3 = (const float*)d_in[7];
    const float* W4 = (const float*)d_in[8];  const float* b4 = (const float*)d_in[9];
    const float* g1 = (const float*)d_in[10]; const float* be1 = (const float*)d_in[11];
    const float* g2 = (const float*)d_in[12]; const float* be2 = (const float*)d_in[13];
    const float* g3 = (const float*)d_in[14]; const float* be3 = (const float*)d_in[15];

    float *p_t1, *p_t2, *p_out, *p_s1, *p_s2, *p_s3, *p_sc, *p_sh;
    __half *p_m1, *p_m2, *p_m3;
    uint32_t* p_wh;
    cudaGetSymbolAddress((void**)&p_t1,  g_t1);
    cudaGetSymbolAddress((void**)&p_t2,  g_t2);
    cudaGetSymbolAddress((void**)&p_out, g_out);
    cudaGetSymbolAddress((void**)&p_s1,  g_s1);
    cudaGetSymbolAddress((void**)&p_s2,  g_s2);
    cudaGetSymbolAddress((void**)&p_s3,  g_s3);
    cudaGetSymbolAddress((void**)&p_sc,  g_scale);
    cudaGetSymbolAddress((void**)&p_sh,  g_shift);
    cudaGetSymbolAddress((void**)&p_m1,  g_m1);
    cudaGetSymbolAddress((void**)&p_m2,  g_m2);
    cudaGetSymbolAddress((void**)&p_m3,  g_m3);
    cudaGetSymbolAddress((void**)&p_wh,  g_wh);

    const int TB = 256;
    const int WPW = 32 * 8 * 128;
    // graph build
    k_init <<<(Nn + TB - 1) / TB, TB>>>();
    k_count<<<(Ee + TB - 1) / TB, TB>>>(ei);
    k_scan1<<<SCB, 1024>>>();
    k_scan3<<<(Nn + TB - 1) / TB, TB>>>();
    k_fill <<<(Ee + TB - 1) / TB, TB>>>(ei);

    // pre-pack combined (monomial-basis) weights for all layers, one launch
    k_wpack3<<<(3 * WPW + TB - 1) / TB, TB>>>(W2, W3, W4, p_wh);

    int gP128 = (Nn + 3) / 4;
    int gGemm = (Nn + BM - 1) / BM;      // 391
    int g12   = (Nn + 31) / 32;          // 1563

    // layer 1 (F=3, Chebyshev form)
    k_prop3<<<(Nn + TB - 1) / TB, TB>>>(x, nullptr, p_s1);
    k_prop3<<<(Nn + TB - 1) / TB, TB>>>(p_s1, x, p_s2);
    k_prop3<<<(Nn + TB - 1) / TB, TB>>>(p_s2, p_s1, p_s3);
    k_gemm12<<<g12, Hd>>>(x, p_s1, p_s2, p_s3, W1, b1, p_out);
    k_bnfin<<<Hd, 256>>>(g1, be1, g12);

    // layer 2: p1 = L(bn(h)), p2 = L p1, p3 = L p2 (pure gathers + mirrors;
    // p3's fp32 copy is never read -> skipped)
    k_prop128<<<gP128, 128>>>(p_out, p_t1, p_m1, p_sc, p_sh, 1);
    k_prop128<<<gP128, 128>>>(p_t1, p_t2, p_m2, nullptr, nullptr, 0);
    k_prop128<<<gP128, 128>>>(p_t2, nullptr, p_m3, nullptr, nullptr, 0);
    k_gemm_mma<<<gGemm, 256>>>(p_out, p_m1, p_m2, p_m3, p_wh + 0 * WPW, b2, p_out, p_sc, p_sh, 1);
    k_bnfin<<<Hd, 256>>>(g2, be2, gGemm);

    // layer 3
    k_prop128<<<gP128, 128>>>(p_out, p_t1, p_m1, p_sc, p_sh, 1);
    k_prop128<<<gP128, 128>>>(p_t1, p_t2, p_m2, nullptr, nullptr, 0);
    k_prop128<<<gP128, 128>>>(p_t2, nullptr, p_m3, nullptr, nullptr, 0);
    k_gemm_mma<<<gGemm, 256>>>(p_out, p_m1, p_m2, p_m3, p_wh + 1 * WPW, b3, p_out, p_sc, p_sh, 2);
    k_bnfin<<<Hd, 256>>>(g3, be3, gGemm);

    // layer 4: props + GEMM with fused row-normalize, straight to d_out
    k_prop128<<<gP128, 128>>>(p_out, p_t1, p_m1, p_sc, p_sh, 1);
    k_prop128<<<gP128, 128>>>(p_t1, p_t2, p_m2, nullptr, nullptr, 0);
    k_prop128<<<gP128, 128>>>(p_t2, nullptr, p_m3, nullptr, nullptr, 0);
    k_gemm_mma<<<gGemm, 256>>>(p_out, p_m1, p_m2, p_m3, p_wh + 2 * WPW, b4, (float*)d_out,
                               p_sc, p_sh, 0);
}